// round 6
// baseline (speedup 1.0000x reference)
#include <cuda_runtime.h>
#include <cuda_bf16.h>

#define CCH 256        // channels
#define LV 2           // levels
#define NP 4           // points
#define NOFF 16        // offset outputs (LV*NP*2)
#define NAW 8          // attn outputs (LV*NP)
#define NOUT 24        // total projection outputs
#define WPB 8          // warps per block (sampling kernel)

// Scratch: per-query projection results {16 raw offsets, 8 normalized attn w}.
__device__ float g_P[1 << 21];   // 8.4 MB, supports Q up to ~87k

// ---------------------------------------------------------------------------
// Kernel 1: projection + softmax.  Warp-cooperative: 8 queries per warp,
// 4 lanes per query (lane s owns channels {16k+4s..16k+4s+3}).  Weights in
// [j][c] smem layout -> each warp LDS.128 is 4 consecutive 16B chunks
// broadcast to 8 query-groups: conflict-free.  Packed f32x2 FMA.
// Combine partial dots with 2 butterfly shuffle steps (xor 1, 2).
// ---------------------------------------------------------------------------
__global__ __launch_bounds__(256)
void proj_kernel(const float* __restrict__ query,
                 const float* __restrict__ W_off,  const float* __restrict__ b_off,
                 const float* __restrict__ W_attn, const float* __restrict__ b_attn,
                 int Q)
{
    __shared__ __align__(16) float wsh[NOUT * CCH];   // [j][c], rows 1KB

    for (int i = threadIdx.x; i < CCH * NOFF; i += 256) {
        int c = i >> 4, j = i & 15;                 // W_off row-major [C,16]
        wsh[j * CCH + c] = W_off[i];
    }
    for (int i = threadIdx.x; i < CCH * NAW; i += 256) {
        int c = i >> 3, j = i & 7;                  // W_attn row-major [C,8]
        wsh[(NOFF + j) * CCH + c] = W_attn[i];
    }
    __syncthreads();

    const int lane = threadIdx.x & 31;
    const int warp = threadIdx.x >> 5;
    const int qq   = lane >> 2;     // query within warp (0..7)
    const int s    = lane & 3;      // channel-quarter (0..3)

    const int q  = blockIdx.x * 64 + warp * 8 + qq;
    const int qc = min(q, Q - 1);   // clamp for safe loads; result discarded

    unsigned long long acc2[NOUT];
#pragma unroll
    for (int j = 0; j < NOUT; j++) acc2[j] = 0ull;

    // lane reads query[qc*256 + 16k + 4s .. +3] each step k
    const float4* q4 = (const float4*)(query + (size_t)qc * CCH) + s;
    const char*   wb = (const char*)wsh + s * 16;

#pragma unroll 2
    for (int k = 0; k < 16; k++) {
        const float4 qv = __ldg(q4 + k * 4);
        unsigned long long q01, q23;
        asm("mov.b64 %0, {%1, %2};" : "=l"(q01) : "f"(qv.x), "f"(qv.y));
        asm("mov.b64 %0, {%1, %2};" : "=l"(q23) : "f"(qv.z), "f"(qv.w));
        const char* wr = wb + k * 64;
#pragma unroll
        for (int j = 0; j < NOUT; j++) {
            const ulonglong2 w = *(const ulonglong2*)(wr + j * (CCH * 4));
            asm("fma.rn.f32x2 %0, %1, %2, %0;" : "+l"(acc2[j]) : "l"(w.x), "l"(q01));
            asm("fma.rn.f32x2 %0, %1, %2, %0;" : "+l"(acc2[j]) : "l"(w.y), "l"(q23));
        }
    }

    float p[NOUT];
#pragma unroll
    for (int j = 0; j < NOUT; j++) {
        float lo, hi;
        asm("mov.b64 {%0, %1}, %2;" : "=f"(lo), "=f"(hi) : "l"(acc2[j]));
        p[j] = lo + hi;
    }
    // combine the 4 channel-quarters (lanes differing in bits 0,1 = same query)
#pragma unroll
    for (int d = 1; d <= 2; d <<= 1) {
#pragma unroll
        for (int j = 0; j < NOUT; j++)
            p[j] += __shfl_xor_sync(0xffffffffu, p[j], d);
    }
#pragma unroll
    for (int j = 0; j < NOFF; j++) p[j] += __ldg(b_off + j);
#pragma unroll
    for (int j = 0; j < NAW; j++)  p[NOFF + j] += __ldg(b_attn + j);

    // softmax over the 8 attn logits (redundant on all 4 lanes of the query)
    float m = p[NOFF];
#pragma unroll
    for (int j = 1; j < NAW; j++) m = fmaxf(m, p[NOFF + j]);
    float sum = 0.f;
#pragma unroll
    for (int j = 0; j < NAW; j++) {
        const float e = __expf(p[NOFF + j] - m);
        p[NOFF + j] = e;
        sum += e;
    }
    const float inv = 1.f / sum;
#pragma unroll
    for (int j = 0; j < NAW; j++) p[NOFF + j] *= inv;

    if (q < Q) {
        float4* o4 = (float4*)(g_P + (size_t)q * NOUT);
        o4[s] = make_float4(p[4 * s], p[4 * s + 1], p[4 * s + 2], p[4 * s + 3]);
        if (s < 2)
            o4[s + 4] = make_float4(p[16 + 4 * s], p[17 + 4 * s],
                                    p[18 + 4 * s], p[19 + 4 * s]);
    }
}

// ---------------------------------------------------------------------------
// Kernel 2: bilinear sampling with corner deduplication.  warp = query.
// (unchanged from round 5 — proven at 64.3us)
// ---------------------------------------------------------------------------
__global__ __launch_bounds__(WPB * 32, 6)
void sample_kernel(const float* __restrict__ value,
                   const float* __restrict__ refpts,
                   const int*   __restrict__ shapes_raw,
                   float* __restrict__ out, int Q)
{
    const int tid  = threadIdx.x;
    const int lane = tid & 31;
    const int q = blockIdx.x * WPB + (tid >> 5);
    if (q >= Q) return;

    // decode spatial shapes (int64 little-endian -> odd int32 slots are 0)
    int HH[LV], WW[LV];
    {
        const int st = (__ldg(shapes_raw + 1) == 0) ? 2 : 1;
#pragma unroll
        for (int l = 0; l < LV; l++) {
            HH[l] = __ldg(shapes_raw + (2 * l) * st);
            WW[l] = __ldg(shapes_raw + (2 * l + 1) * st);
        }
    }

    const float4* pf  = (const float4*)(g_P + (size_t)q * NOUT);
    const float*  ref = refpts + (size_t)q * (LV * 2);

    float4 acc0 = make_float4(0.f, 0.f, 0.f, 0.f);
    float4 acc1 = make_float4(0.f, 0.f, 0.f, 0.f);
    size_t loff = 0;

#define GATHER(XX, YY, W)                                                      \
    do {                                                                       \
        const float4* vp = (const float4*)(vb + ((size_t)(YY) * Ws + (XX)) * CCH); \
        const float4 v0 = __ldg(vp + lane * 2 + 0);                            \
        const float4 v1 = __ldg(vp + lane * 2 + 1);                            \
        acc0.x = fmaf((W), v0.x, acc0.x);                                      \
        acc0.y = fmaf((W), v0.y, acc0.y);                                      \
        acc0.z = fmaf((W), v0.z, acc0.z);                                      \
        acc0.w = fmaf((W), v0.w, acc0.w);                                      \
        acc1.x = fmaf((W), v1.x, acc1.x);                                      \
        acc1.y = fmaf((W), v1.y, acc1.y);                                      \
        acc1.z = fmaf((W), v1.z, acc1.z);                                      \
        acc1.w = fmaf((W), v1.w, acc1.w);                                      \
    } while (0)

#pragma unroll
    for (int l = 0; l < LV; l++) {
        const int Hs = HH[l], Ws = WW[l];
        // ix = (rx + ox/W)*W - 0.5 == rx*W + ox - 0.5
        const float bx = __ldg(ref + 2 * l)     * (float)Ws - 0.5f;
        const float by = __ldg(ref + 2 * l + 1) * (float)Hs - 0.5f;

        const float4 o0 = __ldg(pf + 2 * l);       // offsets pts 0,1 (x,y,x,y)
        const float4 o1 = __ldg(pf + 2 * l + 1);   // offsets pts 2,3
        const float4 wv = __ldg(pf + 4 + l);       // 4 normalized attn weights
        const float* vb = value + loff;

        const float oxs[NP] = {o0.x, o0.z, o1.x, o1.z};
        const float oys[NP] = {o0.y, o0.w, o1.y, o1.w};
        const float aws[NP] = {wv.x, wv.y, wv.z, wv.w};

        int   x0[NP], y0[NP];
        float cw[NP][4];   // w00, w01, w10, w11 per point
#pragma unroll
        for (int pt = 0; pt < NP; pt++) {
            const float ix = bx + oxs[pt];
            const float iy = by + oys[pt];
            const float x0f = floorf(ix);
            const float y0f = floorf(iy);
            x0[pt] = (int)x0f;
            y0[pt] = (int)y0f;
            const float fx = ix - x0f;
            const float fy = iy - y0f;
            const float a  = aws[pt];
            cw[pt][0] = (1.f - fx) * (1.f - fy) * a;
            cw[pt][1] = fx * (1.f - fy) * a;
            cw[pt][2] = (1.f - fx) * fy * a;
            cw[pt][3] = fx * fy * a;
        }

        const int xmin = min(min(x0[0], x0[1]), min(x0[2], x0[3]));
        const int ymin = min(min(y0[0], y0[1]), min(y0[2], y0[3]));
        const int xmax = max(max(x0[0], x0[1]), max(x0[2], x0[3]));
        const int ymax = max(max(y0[0], y0[1]), max(y0[2], y0[3]));

        if (xmax - xmin <= 2 && ymax - ymin <= 2) {
            // Fast path: all 16 corners live in a 4x4 window. Lane i holds the
            // accumulated weight of cell i (cell = dy*4 + dx).
            float myw = 0.f;
#pragma unroll
            for (int pt = 0; pt < NP; pt++) {
                const int b = (y0[pt] - ymin) * 4 + (x0[pt] - xmin);
                myw += (lane == b)     ? cw[pt][0] : 0.f;
                myw += (lane == b + 1) ? cw[pt][1] : 0.f;
                myw += (lane == b + 4) ? cw[pt][2] : 0.f;
                myw += (lane == b + 5) ? cw[pt][3] : 0.f;
            }
            unsigned nz = __ballot_sync(0xffffffffu, (lane < 16) && (myw != 0.f));
            while (nz) {
                const int cell = __ffs(nz) - 1;
                nz &= nz - 1;
                const float w = __shfl_sync(0xffffffffu, myw, cell);
                const int xx = xmin + (cell & 3);
                const int yy = ymin + (cell >> 2);
                if ((unsigned)xx < (unsigned)Ws && (unsigned)yy < (unsigned)Hs)
                    GATHER(xx, yy, w);
            }
        } else {
            // Rare fallback: per-point corner loads.
#pragma unroll
            for (int pt = 0; pt < NP; pt++) {
                const int xs[2] = {x0[pt], x0[pt] + 1};
                const int ys[2] = {y0[pt], y0[pt] + 1};
#pragma unroll
                for (int cy = 0; cy < 2; cy++) {
#pragma unroll
                    for (int cx = 0; cx < 2; cx++) {
                        const int xx = xs[cx];
                        const int yy = ys[cy];
                        const float w = cw[pt][cy * 2 + cx];
                        if ((unsigned)xx < (unsigned)Ws && (unsigned)yy < (unsigned)Hs)
                            GATHER(xx, yy, w);
                    }
                }
            }
        }
        loff += (size_t)Hs * (size_t)Ws * CCH;
    }
#undef GATHER

    float4* op = (float4*)(out + (size_t)q * CCH);
    op[lane * 2 + 0] = acc0;
    op[lane * 2 + 1] = acc1;
}

extern "C" void kernel_launch(void* const* d_in, const int* in_sizes, int n_in,
                              void* d_out, int out_size)
{
    const float* query   = (const float*)d_in[0];
    // d_in[1] = key (unused)
    const float* value   = (const float*)d_in[2];
    const float* refpts  = (const float*)d_in[3];
    const int*   shapes  = (const int*)d_in[4];
    const float* W_off   = (const float*)d_in[5];
    const float* b_off   = (const float*)d_in[6];
    const float* W_attn  = (const float*)d_in[7];
    const float* b_attn  = (const float*)d_in[8];
    float*       out     = (float*)d_out;

    const int Q = in_sizes[0] / CCH;

    proj_kernel<<<(Q + 63) / 64, 256>>>(query, W_off, b_off, W_attn, b_attn, Q);
    sample_kernel<<<(Q + WPB - 1) / WPB, WPB * 32>>>(value, refpts, shapes, out, Q);
}

// round 7
// speedup vs baseline: 1.1909x; 1.1909x over previous
#include <cuda_runtime.h>
#include <cuda_bf16.h>

#define CCH 256        // channels
#define LV 2           // levels
#define NP 4           // points
#define NOFF 16        // offset outputs (LV*NP*2)
#define NAW 8          // attn outputs (LV*NP)
#define NOUT 24        // total projection outputs
#define WPB 8          // warps per block (sampling kernel)
#define K1_BLOCK 128   // threads per block (projection kernel)

// Scratch: per-query projection results {16 raw offsets, 8 normalized attn w}.
__device__ float g_P[1 << 21];   // 8.4 MB, supports Q up to ~87k

// ---------------------------------------------------------------------------
// Kernel 1: projection + softmax.  thread = query.
// Round-5 structure (12 packed f32x2 accumulators, [c][24] smem weights read
// as warp-uniform LDS.128) + batched query prefetch: 16 LDG.128 issued
// back-to-back per 64-channel pass (MLP=16) to hide DRAM latency at the
// grid-limited occupancy of 8.4 warps/SM.
// ---------------------------------------------------------------------------
__global__ __launch_bounds__(K1_BLOCK)
void proj_kernel(const float* __restrict__ query,
                 const float* __restrict__ W_off,  const float* __restrict__ b_off,
                 const float* __restrict__ W_attn, const float* __restrict__ b_attn,
                 int Q)
{
    __shared__ __align__(16) float wsh[CCH * NOUT];   // [c][24], rows 96B

    for (int i = threadIdx.x; i < CCH * NOFF; i += K1_BLOCK) {
        int c = i >> 4, j = i & 15;                 // W_off row-major [C,16]
        wsh[c * NOUT + j] = W_off[i];
    }
    for (int i = threadIdx.x; i < CCH * NAW; i += K1_BLOCK) {
        int c = i >> 3, j = i & 7;                  // W_attn row-major [C,8]
        wsh[c * NOUT + NOFF + j] = W_attn[i];
    }
    __syncthreads();

    const int q = blockIdx.x * K1_BLOCK + threadIdx.x;
    if (q >= Q) return;

    // Pack bias into 12 f32x2 accumulators.
    unsigned long long acc[12];
    {
        float pb[NOUT];
#pragma unroll
        for (int j = 0; j < NOFF; j++) pb[j] = __ldg(b_off + j);
#pragma unroll
        for (int j = 0; j < NAW; j++)  pb[NOFF + j] = __ldg(b_attn + j);
#pragma unroll
        for (int i = 0; i < 12; i++)
            asm("mov.b64 %0, {%1, %2};" : "=l"(acc[i]) : "f"(pb[2 * i]), "f"(pb[2 * i + 1]));
    }

    const float4* q4 = (const float4*)(query + (size_t)q * CCH);
    const char* wrow = (const char*)wsh;

#define PSTEP(QC)                                                              \
    do {                                                                       \
        unsigned long long q2;                                                 \
        asm("mov.b64 %0, {%1, %1};" : "=l"(q2) : "f"(QC));                     \
        const ulonglong2* w2 = (const ulonglong2*)wrow;                        \
        const ulonglong2 a0 = w2[0], a1 = w2[1], a2 = w2[2];                   \
        const ulonglong2 a3 = w2[3], a4 = w2[4], a5 = w2[5];                   \
        asm("fma.rn.f32x2 %0, %1, %2, %0;" : "+l"(acc[0])  : "l"(a0.x), "l"(q2)); \
        asm("fma.rn.f32x2 %0, %1, %2, %0;" : "+l"(acc[1])  : "l"(a0.y), "l"(q2)); \
        asm("fma.rn.f32x2 %0, %1, %2, %0;" : "+l"(acc[2])  : "l"(a1.x), "l"(q2)); \
        asm("fma.rn.f32x2 %0, %1, %2, %0;" : "+l"(acc[3])  : "l"(a1.y), "l"(q2)); \
        asm("fma.rn.f32x2 %0, %1, %2, %0;" : "+l"(acc[4])  : "l"(a2.x), "l"(q2)); \
        asm("fma.rn.f32x2 %0, %1, %2, %0;" : "+l"(acc[5])  : "l"(a2.y), "l"(q2)); \
        asm("fma.rn.f32x2 %0, %1, %2, %0;" : "+l"(acc[6])  : "l"(a3.x), "l"(q2)); \
        asm("fma.rn.f32x2 %0, %1, %2, %0;" : "+l"(acc[7])  : "l"(a3.y), "l"(q2)); \
        asm("fma.rn.f32x2 %0, %1, %2, %0;" : "+l"(acc[8])  : "l"(a4.x), "l"(q2)); \
        asm("fma.rn.f32x2 %0, %1, %2, %0;" : "+l"(acc[9])  : "l"(a4.y), "l"(q2)); \
        asm("fma.rn.f32x2 %0, %1, %2, %0;" : "+l"(acc[10]) : "l"(a5.x), "l"(q2)); \
        asm("fma.rn.f32x2 %0, %1, %2, %0;" : "+l"(acc[11]) : "l"(a5.y), "l"(q2)); \
        wrow += NOUT * 4;                                                      \
    } while (0)

#pragma unroll
    for (int pass = 0; pass < 4; pass++) {
        // Batch-issue 16 independent LDG.128 (one 64-channel chunk, MLP=16).
        float4 qr[16];
#pragma unroll
        for (int i = 0; i < 16; i++) qr[i] = __ldg(q4 + pass * 16 + i);
#pragma unroll
        for (int i = 0; i < 16; i++) {
            PSTEP(qr[i].x);
            PSTEP(qr[i].y);
            PSTEP(qr[i].z);
            PSTEP(qr[i].w);
        }
    }
#undef PSTEP

    float p[NOUT];
#pragma unroll
    for (int i = 0; i < 12; i++) {
        float lo, hi;
        asm("mov.b64 {%0, %1}, %2;" : "=f"(lo), "=f"(hi) : "l"(acc[i]));
        p[2 * i] = lo; p[2 * i + 1] = hi;
    }

    // softmax over the 8 attn logits (store normalized)
    float m = p[NOFF];
#pragma unroll
    for (int j = 1; j < NAW; j++) m = fmaxf(m, p[NOFF + j]);
    float s = 0.f;
#pragma unroll
    for (int j = 0; j < NAW; j++) {
        const float e = __expf(p[NOFF + j] - m);
        p[NOFF + j] = e;
        s += e;
    }
    const float inv = 1.f / s;
#pragma unroll
    for (int j = 0; j < NAW; j++) p[NOFF + j] *= inv;

    float4* o4 = (float4*)(g_P + (size_t)q * NOUT);
#pragma unroll
    for (int i = 0; i < 6; i++)
        o4[i] = make_float4(p[4 * i], p[4 * i + 1], p[4 * i + 2], p[4 * i + 3]);
}

// ---------------------------------------------------------------------------
// Kernel 2: bilinear sampling with corner deduplication.  warp = query.
// (unchanged — proven at 63.5us)
// ---------------------------------------------------------------------------
__global__ __launch_bounds__(WPB * 32, 6)
void sample_kernel(const float* __restrict__ value,
                   const float* __restrict__ refpts,
                   const int*   __restrict__ shapes_raw,
                   float* __restrict__ out, int Q)
{
    const int tid  = threadIdx.x;
    const int lane = tid & 31;
    const int q = blockIdx.x * WPB + (tid >> 5);
    if (q >= Q) return;

    // decode spatial shapes (int64 little-endian -> odd int32 slots are 0)
    int HH[LV], WW[LV];
    {
        const int st = (__ldg(shapes_raw + 1) == 0) ? 2 : 1;
#pragma unroll
        for (int l = 0; l < LV; l++) {
            HH[l] = __ldg(shapes_raw + (2 * l) * st);
            WW[l] = __ldg(shapes_raw + (2 * l + 1) * st);
        }
    }

    const float4* pf  = (const float4*)(g_P + (size_t)q * NOUT);
    const float*  ref = refpts + (size_t)q * (LV * 2);

    float4 acc0 = make_float4(0.f, 0.f, 0.f, 0.f);
    float4 acc1 = make_float4(0.f, 0.f, 0.f, 0.f);
    size_t loff = 0;

#define GATHER(XX, YY, W)                                                      \
    do {                                                                       \
        const float4* vp = (const float4*)(vb + ((size_t)(YY) * Ws + (XX)) * CCH); \
        const float4 v0 = __ldg(vp + lane * 2 + 0);                            \
        const float4 v1 = __ldg(vp + lane * 2 + 1);                            \
        acc0.x = fmaf((W), v0.x, acc0.x);                                      \
        acc0.y = fmaf((W), v0.y, acc0.y);                                      \
        acc0.z = fmaf((W), v0.z, acc0.z);                                      \
        acc0.w = fmaf((W), v0.w, acc0.w);                                      \
        acc1.x = fmaf((W), v1.x, acc1.x);                                      \
        acc1.y = fmaf((W), v1.y, acc1.y);                                      \
        acc1.z = fmaf((W), v1.z, acc1.z);                                      \
        acc1.w = fmaf((W), v1.w, acc1.w);                                      \
    } while (0)

#pragma unroll
    for (int l = 0; l < LV; l++) {
        const int Hs = HH[l], Ws = WW[l];
        // ix = (rx + ox/W)*W - 0.5 == rx*W + ox - 0.5
        const float bx = __ldg(ref + 2 * l)     * (float)Ws - 0.5f;
        const float by = __ldg(ref + 2 * l + 1) * (float)Hs - 0.5f;

        const float4 o0 = __ldg(pf + 2 * l);       // offsets pts 0,1 (x,y,x,y)
        const float4 o1 = __ldg(pf + 2 * l + 1);   // offsets pts 2,3
        const float4 wv = __ldg(pf + 4 + l);       // 4 normalized attn weights
        const float* vb = value + loff;

        const float oxs[NP] = {o0.x, o0.z, o1.x, o1.z};
        const float oys[NP] = {o0.y, o0.w, o1.y, o1.w};
        const float aws[NP] = {wv.x, wv.y, wv.z, wv.w};

        int   x0[NP], y0[NP];
        float cw[NP][4];   // w00, w01, w10, w11 per point
#pragma unroll
        for (int pt = 0; pt < NP; pt++) {
            const float ix = bx + oxs[pt];
            const float iy = by + oys[pt];
            const float x0f = floorf(ix);
            const float y0f = floorf(iy);
            x0[pt] = (int)x0f;
            y0[pt] = (int)y0f;
            const float fx = ix - x0f;
            const float fy = iy - y0f;
            const float a  = aws[pt];
            cw[pt][0] = (1.f - fx) * (1.f - fy) * a;
            cw[pt][1] = fx * (1.f - fy) * a;
            cw[pt][2] = (1.f - fx) * fy * a;
            cw[pt][3] = fx * fy * a;
        }

        const int xmin = min(min(x0[0], x0[1]), min(x0[2], x0[3]));
        const int ymin = min(min(y0[0], y0[1]), min(y0[2], y0[3]));
        const int xmax = max(max(x0[0], x0[1]), max(x0[2], x0[3]));
        const int ymax = max(max(y0[0], y0[1]), max(y0[2], y0[3]));

        if (xmax - xmin <= 2 && ymax - ymin <= 2) {
            // Fast path: all 16 corners live in a 4x4 window. Lane i holds the
            // accumulated weight of cell i (cell = dy*4 + dx).
            float myw = 0.f;
#pragma unroll
            for (int pt = 0; pt < NP; pt++) {
                const int b = (y0[pt] - ymin) * 4 + (x0[pt] - xmin);
                myw += (lane == b)     ? cw[pt][0] : 0.f;
                myw += (lane == b + 1) ? cw[pt][1] : 0.f;
                myw += (lane == b + 4) ? cw[pt][2] : 0.f;
                myw += (lane == b + 5) ? cw[pt][3] : 0.f;
            }
            unsigned nz = __ballot_sync(0xffffffffu, (lane < 16) && (myw != 0.f));
            while (nz) {
                const int cell = __ffs(nz) - 1;
                nz &= nz - 1;
                const float w = __shfl_sync(0xffffffffu, myw, cell);
                const int xx = xmin + (cell & 3);
                const int yy = ymin + (cell >> 2);
                if ((unsigned)xx < (unsigned)Ws && (unsigned)yy < (unsigned)Hs)
                    GATHER(xx, yy, w);
            }
        } else {
            // Rare fallback: per-point corner loads.
#pragma unroll
            for (int pt = 0; pt < NP; pt++) {
                const int xs[2] = {x0[pt], x0[pt] + 1};
                const int ys[2] = {y0[pt], y0[pt] + 1};
#pragma unroll
                for (int cy = 0; cy < 2; cy++) {
#pragma unroll
                    for (int cx = 0; cx < 2; cx++) {
                        const int xx = xs[cx];
                        const int yy = ys[cy];
                        const float w = cw[pt][cy * 2 + cx];
                        if ((unsigned)xx < (unsigned)Ws && (unsigned)yy < (unsigned)Hs)
                            GATHER(xx, yy, w);
                    }
                }
            }
        }
        loff += (size_t)Hs * (size_t)Ws * CCH;
    }
#undef GATHER

    float4* op = (float4*)(out + (size_t)q * CCH);
    op[lane * 2 + 0] = acc0;
    op[lane * 2 + 1] = acc1;
}

extern "C" void kernel_launch(void* const* d_in, const int* in_sizes, int n_in,
                              void* d_out, int out_size)
{
    const float* query   = (const float*)d_in[0];
    // d_in[1] = key (unused)
    const float* value   = (const float*)d_in[2];
    const float* refpts  = (const float*)d_in[3];
    const int*   shapes  = (const int*)d_in[4];
    const float* W_off   = (const float*)d_in[5];
    const float* b_off   = (const float*)d_in[6];
    const float* W_attn  = (const float*)d_in[7];
    const float* b_attn  = (const float*)d_in[8];
    float*       out     = (float*)d_out;

    const int Q = in_sizes[0] / CCH;

    proj_kernel<<<(Q + K1_BLOCK - 1) / K1_BLOCK, K1_BLOCK>>>(
        query, W_off, b_off, W_attn, b_attn, Q);
    sample_kernel<<<(Q + WPB - 1) / WPB, WPB * 32>>>(
        value, refpts, shapes, out, Q);
}

// round 8
// speedup vs baseline: 1.2586x; 1.0568x over previous
#include <cuda_runtime.h>
#include <cuda_bf16.h>

#define CCH 256        // channels
#define LV 2           // levels
#define NP 4           // points
#define NOFF 16        // offset outputs (LV*NP*2)
#define NAW 8          // attn outputs (LV*NP)
#define NOUT 24        // total projection outputs
#define WPB 8          // warps per block (sampling kernel)

// Scratch: per-query projection results {16 raw offsets, 8 normalized attn w}.
__device__ float g_P[1 << 21];   // 8.4 MB, supports Q up to ~87k

// ---------------------------------------------------------------------------
// Kernel 1: projection + softmax.  2-way K-split: 256-thread block handles
// 128 queries; thread t (<128) does channels [0,128) of query q, thread
// t+128 does channels [128,256) of the same q.  Doubles warp count vs
// thread-per-query (16.9/SM) and halves per-thread latency chains.
// 12 packed f32x2 accumulators; weights [c][24] in smem (uniform LDS.128).
// ---------------------------------------------------------------------------
__global__ __launch_bounds__(256)
void proj_kernel(const float* __restrict__ query,
                 const float* __restrict__ W_off,  const float* __restrict__ b_off,
                 const float* __restrict__ W_attn, const float* __restrict__ b_attn,
                 int Q)
{
    __shared__ __align__(16) float wsh[CCH * NOUT];     // [c][24], 24KB
    __shared__ float psum[128][NOUT + 1];               // partner partials, ~12.5KB

    for (int i = threadIdx.x; i < CCH * NOFF; i += 256) {
        int c = i >> 4, j = i & 15;                 // W_off row-major [C,16]
        wsh[c * NOUT + j] = W_off[i];
    }
    for (int i = threadIdx.x; i < CCH * NAW; i += 256) {
        int c = i >> 3, j = i & 7;                  // W_attn row-major [C,8]
        wsh[c * NOUT + NOFF + j] = W_attn[i];
    }
    __syncthreads();

    const int t    = threadIdx.x;
    const int qloc = t & 127;                 // query within block
    const int half = t >> 7;                  // 0: channels [0,128), 1: [128,256)
    const int q    = blockIdx.x * 128 + qloc;
    const int qc   = min(q, Q - 1);           // clamp loads; stores guarded

    unsigned long long acc[12];
#pragma unroll
    for (int i = 0; i < 12; i++) acc[i] = 0ull;

    const float4* q4 = (const float4*)(query + (size_t)qc * CCH) + half * 32;
    const char* wrow = (const char*)wsh + half * 128 * (NOUT * 4);

#define PSTEP(QC)                                                              \
    do {                                                                       \
        unsigned long long q2;                                                 \
        asm("mov.b64 %0, {%1, %1};" : "=l"(q2) : "f"(QC));                     \
        const ulonglong2* w2 = (const ulonglong2*)wrow;                        \
        const ulonglong2 a0 = w2[0], a1 = w2[1], a2 = w2[2];                   \
        const ulonglong2 a3 = w2[3], a4 = w2[4], a5 = w2[5];                   \
        asm("fma.rn.f32x2 %0, %1, %2, %0;" : "+l"(acc[0])  : "l"(a0.x), "l"(q2)); \
        asm("fma.rn.f32x2 %0, %1, %2, %0;" : "+l"(acc[1])  : "l"(a0.y), "l"(q2)); \
        asm("fma.rn.f32x2 %0, %1, %2, %0;" : "+l"(acc[2])  : "l"(a1.x), "l"(q2)); \
        asm("fma.rn.f32x2 %0, %1, %2, %0;" : "+l"(acc[3])  : "l"(a1.y), "l"(q2)); \
        asm("fma.rn.f32x2 %0, %1, %2, %0;" : "+l"(acc[4])  : "l"(a2.x), "l"(q2)); \
        asm("fma.rn.f32x2 %0, %1, %2, %0;" : "+l"(acc[5])  : "l"(a2.y), "l"(q2)); \
        asm("fma.rn.f32x2 %0, %1, %2, %0;" : "+l"(acc[6])  : "l"(a3.x), "l"(q2)); \
        asm("fma.rn.f32x2 %0, %1, %2, %0;" : "+l"(acc[7])  : "l"(a3.y), "l"(q2)); \
        asm("fma.rn.f32x2 %0, %1, %2, %0;" : "+l"(acc[8])  : "l"(a4.x), "l"(q2)); \
        asm("fma.rn.f32x2 %0, %1, %2, %0;" : "+l"(acc[9])  : "l"(a4.y), "l"(q2)); \
        asm("fma.rn.f32x2 %0, %1, %2, %0;" : "+l"(acc[10]) : "l"(a5.x), "l"(q2)); \
        asm("fma.rn.f32x2 %0, %1, %2, %0;" : "+l"(acc[11]) : "l"(a5.y), "l"(q2)); \
        wrow += NOUT * 4;                                                      \
    } while (0)

#pragma unroll
    for (int pass = 0; pass < 4; pass++) {
        float4 qr[8];                 // batch 8 LDG.128 (MLP=8)
#pragma unroll
        for (int i = 0; i < 8; i++) qr[i] = __ldg(q4 + pass * 8 + i);
#pragma unroll
        for (int i = 0; i < 8; i++) {
            PSTEP(qr[i].x);
            PSTEP(qr[i].y);
            PSTEP(qr[i].z);
            PSTEP(qr[i].w);
        }
    }
#undef PSTEP

    float p[NOUT];
#pragma unroll
    for (int i = 0; i < 12; i++) {
        float lo, hi;
        asm("mov.b64 {%0, %1}, %2;" : "=f"(lo), "=f"(hi) : "l"(acc[i]));
        p[2 * i] = lo; p[2 * i + 1] = hi;
    }

    // combine halves via smem
    if (half) {
#pragma unroll
        for (int j = 0; j < NOUT; j++) psum[qloc][j] = p[j];
    }
    __syncthreads();
    if (half) return;
#pragma unroll
    for (int j = 0; j < NOUT; j++) p[j] += psum[qloc][j];
#pragma unroll
    for (int j = 0; j < NOFF; j++) p[j] += __ldg(b_off + j);
#pragma unroll
    for (int j = 0; j < NAW; j++)  p[NOFF + j] += __ldg(b_attn + j);

    // softmax over the 8 attn logits (store normalized)
    float m = p[NOFF];
#pragma unroll
    for (int j = 1; j < NAW; j++) m = fmaxf(m, p[NOFF + j]);
    float s = 0.f;
#pragma unroll
    for (int j = 0; j < NAW; j++) {
        const float e = __expf(p[NOFF + j] - m);
        p[NOFF + j] = e;
        s += e;
    }
    const float inv = 1.f / s;
#pragma unroll
    for (int j = 0; j < NAW; j++) p[NOFF + j] *= inv;

    if (q < Q) {
        float4* o4 = (float4*)(g_P + (size_t)q * NOUT);
#pragma unroll
        for (int i = 0; i < 6; i++)
            o4[i] = make_float4(p[4 * i], p[4 * i + 1], p[4 * i + 2], p[4 * i + 3]);
    }
}

// ---------------------------------------------------------------------------
// Kernel 2: bilinear sampling with corner deduplication.  warp = query.
// Packed lane mapping: first LDG.128 covers bytes [0,512) of the 1KB row
// (lane*16), second covers [512,1024) -> each instruction hits 4 fully
// packed 128B lines (half the L1 wavefronts of the old 32B-stride layout).
// Lane owns channels [4*lane,4*lane+4) and [128+4*lane, 128+4*lane+4).
// ---------------------------------------------------------------------------
__global__ __launch_bounds__(WPB * 32, 6)
void sample_kernel(const float* __restrict__ value,
                   const float* __restrict__ refpts,
                   const int*   __restrict__ shapes_raw,
                   float* __restrict__ out, int Q)
{
    const int tid  = threadIdx.x;
    const int lane = tid & 31;
    const int q = blockIdx.x * WPB + (tid >> 5);
    if (q >= Q) return;

    // decode spatial shapes (int64 little-endian -> odd int32 slots are 0)
    int HH[LV], WW[LV];
    {
        const int st = (__ldg(shapes_raw + 1) == 0) ? 2 : 1;
#pragma unroll
        for (int l = 0; l < LV; l++) {
            HH[l] = __ldg(shapes_raw + (2 * l) * st);
            WW[l] = __ldg(shapes_raw + (2 * l + 1) * st);
        }
    }

    const float4* pf  = (const float4*)(g_P + (size_t)q * NOUT);
    const float*  ref = refpts + (size_t)q * (LV * 2);

    float4 acc0 = make_float4(0.f, 0.f, 0.f, 0.f);
    float4 acc1 = make_float4(0.f, 0.f, 0.f, 0.f);
    size_t loff = 0;

#define GATHER(XX, YY, W)                                                      \
    do {                                                                       \
        const float4* vp = (const float4*)(vb + ((size_t)(YY) * Ws + (XX)) * CCH); \
        const float4 v0 = __ldg(vp + lane);                                    \
        const float4 v1 = __ldg(vp + 32 + lane);                               \
        acc0.x = fmaf((W), v0.x, acc0.x);                                      \
        acc0.y = fmaf((W), v0.y, acc0.y);                                      \
        acc0.z = fmaf((W), v0.z, acc0.z);                                      \
        acc0.w = fmaf((W), v0.w, acc0.w);                                      \
        acc1.x = fmaf((W), v1.x, acc1.x);                                      \
        acc1.y = fmaf((W), v1.y, acc1.y);                                      \
        acc1.z = fmaf((W), v1.z, acc1.z);                                      \
        acc1.w = fmaf((W), v1.w, acc1.w);                                      \
    } while (0)

#pragma unroll
    for (int l = 0; l < LV; l++) {
        const int Hs = HH[l], Ws = WW[l];
        // ix = (rx + ox/W)*W - 0.5 == rx*W + ox - 0.5
        const float bx = __ldg(ref + 2 * l)     * (float)Ws - 0.5f;
        const float by = __ldg(ref + 2 * l + 1) * (float)Hs - 0.5f;

        const float4 o0 = __ldg(pf + 2 * l);       // offsets pts 0,1 (x,y,x,y)
        const float4 o1 = __ldg(pf + 2 * l + 1);   // offsets pts 2,3
        const float4 wv = __ldg(pf + 4 + l);       // 4 normalized attn weights
        const float* vb = value + loff;

        const float oxs[NP] = {o0.x, o0.z, o1.x, o1.z};
        const float oys[NP] = {o0.y, o0.w, o1.y, o1.w};
        const float aws[NP] = {wv.x, wv.y, wv.z, wv.w};

        int   x0[NP], y0[NP];
        float cw[NP][4];   // w00, w01, w10, w11 per point
#pragma unroll
        for (int pt = 0; pt < NP; pt++) {
            const float ix = bx + oxs[pt];
            const float iy = by + oys[pt];
            const float x0f = floorf(ix);
            const float y0f = floorf(iy);
            x0[pt] = (int)x0f;
            y0[pt] = (int)y0f;
            const float fx = ix - x0f;
            const float fy = iy - y0f;
            const float a  = aws[pt];
            cw[pt][0] = (1.f - fx) * (1.f - fy) * a;
            cw[pt][1] = fx * (1.f - fy) * a;
            cw[pt][2] = (1.f - fx) * fy * a;
            cw[pt][3] = fx * fy * a;
        }

        const int xmin = min(min(x0[0], x0[1]), min(x0[2], x0[3]));
        const int ymin = min(min(y0[0], y0[1]), min(y0[2], y0[3]));
        const int xmax = max(max(x0[0], x0[1]), max(x0[2], x0[3]));
        const int ymax = max(max(y0[0], y0[1]), max(y0[2], y0[3]));

        if (xmax - xmin <= 2 && ymax - ymin <= 2) {
            // Fast path: all 16 corners live in a 4x4 window. Lane i holds the
            // accumulated weight of cell i (cell = dy*4 + dx).
            float myw = 0.f;
#pragma unroll
            for (int pt = 0; pt < NP; pt++) {
                const int b = (y0[pt] - ymin) * 4 + (x0[pt] - xmin);
                myw += (lane == b)     ? cw[pt][0] : 0.f;
                myw += (lane == b + 1) ? cw[pt][1] : 0.f;
                myw += (lane == b + 4) ? cw[pt][2] : 0.f;
                myw += (lane == b + 5) ? cw[pt][3] : 0.f;
            }
            unsigned nz = __ballot_sync(0xffffffffu, (lane < 16) && (myw != 0.f));
            while (nz) {
                const int cell = __ffs(nz) - 1;
                nz &= nz - 1;
                const float w = __shfl_sync(0xffffffffu, myw, cell);
                const int xx = xmin + (cell & 3);
                const int yy = ymin + (cell >> 2);
                if ((unsigned)xx < (unsigned)Ws && (unsigned)yy < (unsigned)Hs)
                    GATHER(xx, yy, w);
            }
        } else {
            // Rare fallback: per-point corner loads.
#pragma unroll
            for (int pt = 0; pt < NP; pt++) {
                const int xs[2] = {x0[pt], x0[pt] + 1};
                const int ys[2] = {y0[pt], y0[pt] + 1};
#pragma unroll
                for (int cy = 0; cy < 2; cy++) {
#pragma unroll
                    for (int cx = 0; cx < 2; cx++) {
                        const int xx = xs[cx];
                        const int yy = ys[cy];
                        const float w = cw[pt][cy * 2 + cx];
                        if ((unsigned)xx < (unsigned)Ws && (unsigned)yy < (unsigned)Hs)
                            GATHER(xx, yy, w);
                    }
                }
            }
        }
        loff += (size_t)Hs * (size_t)Ws * CCH;
    }
#undef GATHER

    float4* op = (float4*)(out + (size_t)q * CCH);
    op[lane]      = acc0;   // channels [4*lane, 4*lane+4)
    op[32 + lane] = acc1;   // channels [128+4*lane, ...)
}

extern "C" void kernel_launch(void* const* d_in, const int* in_sizes, int n_in,
                              void* d_out, int out_size)
{
    const float* query   = (const float*)d_in[0];
    // d_in[1] = key (unused)
    const float* value   = (const float*)d_in[2];
    const float* refpts  = (const float*)d_in[3];
    const int*   shapes  = (const int*)d_in[4];
    const float* W_off   = (const float*)d_in[5];
    const float* b_off   = (const float*)d_in[6];
    const float* W_attn  = (const float*)d_in[7];
    const float* b_attn  = (const float*)d_in[8];
    float*       out     = (float*)d_out;

    const int Q = in_sizes[0] / CCH;

    proj_kernel<<<(Q + 127) / 128, 256>>>(query, W_off, b_off, W_attn, b_attn, Q);
    sample_kernel<<<(Q + WPB - 1) / WPB, WPB * 32>>>(value, refpts, shapes, out, Q);
}

// round 9
// speedup vs baseline: 1.5742x; 1.2508x over previous
#include <cuda_runtime.h>
#include <cuda_bf16.h>

#define CCH 256        // channels
#define LV 2           // levels
#define NP 4           // points
#define NOFF 16        // offset outputs (LV*NP*2)
#define NAW 8          // attn outputs (LV*NP)
#define NOUT 24        // total projection outputs
#define WPB 8          // warps per block (sampling kernel)
#define NKT 32         // k-tiles (256 / 8)
#define NNT 3          // n-tiles (24 / 8)

// Scratch: per-query projection results {16 raw offsets, 8 normalized attn w}.
__device__ float g_P[1 << 21];   // 8.4 MB, supports Q up to ~87k

__device__ __forceinline__ unsigned f2tf32(float f) {
    unsigned r;
    asm("cvt.rna.tf32.f32 %0, %1;" : "=r"(r) : "f"(f));
    return r;
}

__device__ __forceinline__ void mma_tf32(float d[4],
                                         unsigned a0, unsigned a1,
                                         unsigned a2, unsigned a3,
                                         unsigned b0, unsigned b1) {
    asm("mma.sync.aligned.m16n8k8.row.col.f32.tf32.tf32.f32 "
        "{%0,%1,%2,%3}, {%4,%5,%6,%7}, {%8,%9}, {%0,%1,%2,%3};"
        : "+f"(d[0]), "+f"(d[1]), "+f"(d[2]), "+f"(d[3])
        : "r"(a0), "r"(a1), "r"(a2), "r"(a3), "r"(b0), "r"(b1));
}

// ---------------------------------------------------------------------------
// Kernel 1: projection + softmax via tf32 tensor-core MMA.
// Block = 256 threads = 8 warps; each warp computes 16 queries x 24 outputs.
// B fragments (weights) pre-swizzled in smem -> conflict-free LDS.32.
// ---------------------------------------------------------------------------
__global__ __launch_bounds__(256)
void proj_kernel(const float* __restrict__ query,
                 const float* __restrict__ W_off,  const float* __restrict__ b_off,
                 const float* __restrict__ W_attn, const float* __restrict__ b_attn,
                 int Q)
{
    __shared__ unsigned b0sm[NKT * NNT * 32];     // 12KB
    __shared__ unsigned b1sm[NKT * NNT * 32];     // 12KB
    __shared__ float    csm[8][16][28];           // 14KB epilogue staging

    // Stage pre-swizzled B fragments: entry (ktile, ntile, lane) holds
    // W[k][n] with k = ktile*8 + (lane&3) (+4 for b1), n = ntile*8 + (lane>>2).
    for (int idx = threadIdx.x; idx < NKT * NNT * 32; idx += 256) {
        const int ln   = idx & 31;
        const int pair = idx >> 5;
        const int kt   = pair / 3;
        const int nt   = pair - kt * 3;
        const int tig  = ln & 3;
        const int gid  = ln >> 2;
        const int n    = nt * 8 + gid;
        const int k0   = kt * 8 + tig;
        const int k1   = k0 + 4;
        float w0, w1;
        if (n < NOFF) {
            w0 = __ldg(W_off + k0 * NOFF + n);
            w1 = __ldg(W_off + k1 * NOFF + n);
        } else {
            w0 = __ldg(W_attn + k0 * NAW + (n - NOFF));
            w1 = __ldg(W_attn + k1 * NAW + (n - NOFF));
        }
        b0sm[idx] = f2tf32(w0);
        b1sm[idx] = f2tf32(w1);
    }
    __syncthreads();

    const int tid  = threadIdx.x;
    const int lane = tid & 31;
    const int warp = tid >> 5;
    const int gid  = lane >> 2;     // group id (row within 8)
    const int tig  = lane & 3;      // thread-in-group (col within 4)

    const int qbase = blockIdx.x * 128 + warp * 16;
    const int qr0 = min(qbase + gid,     Q - 1);   // clamp loads
    const int qr1 = min(qbase + gid + 8, Q - 1);
    const float* q0p = query + (size_t)qr0 * CCH;
    const float* q1p = query + (size_t)qr1 * CCH;

    float d[NNT][4];
#pragma unroll
    for (int nt = 0; nt < NNT; nt++)
#pragma unroll
        for (int i = 0; i < 4; i++) d[nt][i] = 0.f;

#pragma unroll
    for (int kt4 = 0; kt4 < NKT / 4; kt4++) {
        unsigned af[4][4];
#pragma unroll
        for (int i = 0; i < 4; i++) {
            const int kc = (kt4 * 4 + i) * 8 + tig;
            af[i][0] = f2tf32(__ldg(q0p + kc));
            af[i][1] = f2tf32(__ldg(q1p + kc));
            af[i][2] = f2tf32(__ldg(q0p + kc + 4));
            af[i][3] = f2tf32(__ldg(q1p + kc + 4));
        }
#pragma unroll
        for (int i = 0; i < 4; i++) {
            const int kt = kt4 * 4 + i;
#pragma unroll
            for (int nt = 0; nt < NNT; nt++) {
                const int bidx = (kt * 3 + nt) * 32 + lane;
                mma_tf32(d[nt], af[i][0], af[i][1], af[i][2], af[i][3],
                         b0sm[bidx], b1sm[bidx]);
            }
        }
    }

    // Scatter C fragments to smem: c0/c1 -> row gid, c2/c3 -> row gid+8,
    // cols nt*8 + 2*tig (+1).
#pragma unroll
    for (int nt = 0; nt < NNT; nt++) {
        const int col = nt * 8 + 2 * tig;
        csm[warp][gid][col]         = d[nt][0];
        csm[warp][gid][col + 1]     = d[nt][1];
        csm[warp][gid + 8][col]     = d[nt][2];
        csm[warp][gid + 8][col + 1] = d[nt][3];
    }
    __syncwarp();

    if (lane < 16) {
        const int q = qbase + lane;
        if (q < Q) {
            float p[NOUT];
#pragma unroll
            for (int j = 0; j < NOUT; j++) p[j] = csm[warp][lane][j];
#pragma unroll
            for (int j = 0; j < NOFF; j++) p[j] += __ldg(b_off + j);
#pragma unroll
            for (int j = 0; j < NAW; j++)  p[NOFF + j] += __ldg(b_attn + j);

            float m = p[NOFF];
#pragma unroll
            for (int j = 1; j < NAW; j++) m = fmaxf(m, p[NOFF + j]);
            float s = 0.f;
#pragma unroll
            for (int j = 0; j < NAW; j++) {
                const float e = __expf(p[NOFF + j] - m);
                p[NOFF + j] = e;
                s += e;
            }
            const float inv = 1.f / s;
#pragma unroll
            for (int j = 0; j < NAW; j++) p[NOFF + j] *= inv;

            float4* o4 = (float4*)(g_P + (size_t)q * NOUT);
#pragma unroll
            for (int i = 0; i < 6; i++)
                o4[i] = make_float4(p[4 * i], p[4 * i + 1],
                                    p[4 * i + 2], p[4 * i + 3]);
        }
    }
}

// ---------------------------------------------------------------------------
// Kernel 2: bilinear sampling with corner deduplication.  warp = query.
// Packed lane mapping (R8, proven); 32-bit gather offset math.
// ---------------------------------------------------------------------------
__global__ __launch_bounds__(WPB * 32, 6)
void sample_kernel(const float* __restrict__ value,
                   const float* __restrict__ refpts,
                   const int*   __restrict__ shapes_raw,
                   float* __restrict__ out, int Q)
{
    const int tid  = threadIdx.x;
    const int lane = tid & 31;
    const int q = blockIdx.x * WPB + (tid >> 5);
    if (q >= Q) return;

    // decode spatial shapes (int64 little-endian -> odd int32 slots are 0)
    int HH[LV], WW[LV];
    {
        const int st = (__ldg(shapes_raw + 1) == 0) ? 2 : 1;
#pragma unroll
        for (int l = 0; l < LV; l++) {
            HH[l] = __ldg(shapes_raw + (2 * l) * st);
            WW[l] = __ldg(shapes_raw + (2 * l + 1) * st);
        }
    }

    const float4* pf  = (const float4*)(g_P + (size_t)q * NOUT);
    const float*  ref = refpts + (size_t)q * (LV * 2);

    float4 acc0 = make_float4(0.f, 0.f, 0.f, 0.f);
    float4 acc1 = make_float4(0.f, 0.f, 0.f, 0.f);
    size_t loff = 0;

#define GATHER(XX, YY, W)                                                      \
    do {                                                                       \
        const unsigned off4 = (((unsigned)(YY) * (unsigned)Ws + (unsigned)(XX)) << 6); \
        const float4 v0 = __ldg(vb4 + off4 + lane);                            \
        const float4 v1 = __ldg(vb4 + off4 + 32 + lane);                       \
        acc0.x = fmaf((W), v0.x, acc0.x);                                      \
        acc0.y = fmaf((W), v0.y, acc0.y);                                      \
        acc0.z = fmaf((W), v0.z, acc0.z);                                      \
        acc0.w = fmaf((W), v0.w, acc0.w);                                      \
        acc1.x = fmaf((W), v1.x, acc1.x);                                      \
        acc1.y = fmaf((W), v1.y, acc1.y);                                      \
        acc1.z = fmaf((W), v1.z, acc1.z);                                      \
        acc1.w = fmaf((W), v1.w, acc1.w);                                      \
    } while (0)

#pragma unroll
    for (int l = 0; l < LV; l++) {
        const int Hs = HH[l], Ws = WW[l];
        // ix = (rx + ox/W)*W - 0.5 == rx*W + ox - 0.5
        const float bx = __ldg(ref + 2 * l)     * (float)Ws - 0.5f;
        const float by = __ldg(ref + 2 * l + 1) * (float)Hs - 0.5f;

        const float4 o0 = __ldg(pf + 2 * l);       // offsets pts 0,1 (x,y,x,y)
        const float4 o1 = __ldg(pf + 2 * l + 1);   // offsets pts 2,3
        const float4 wv = __ldg(pf + 4 + l);       // 4 normalized attn weights
        const float4* vb4 = (const float4*)(value + loff);

        const float oxs[NP] = {o0.x, o0.z, o1.x, o1.z};
        const float oys[NP] = {o0.y, o0.w, o1.y, o1.w};
        const float aws[NP] = {wv.x, wv.y, wv.z, wv.w};

        int   x0[NP], y0[NP];
        float cw[NP][4];   // w00, w01, w10, w11 per point
#pragma unroll
        for (int pt = 0; pt < NP; pt++) {
            const float ix = bx + oxs[pt];
            const float iy = by + oys[pt];
            const float x0f = floorf(ix);
            const float y0f = floorf(iy);
            x0[pt] = (int)x0f;
            y0[pt] = (int)y0f;
            const float fx = ix - x0f;
            const float fy = iy - y0f;
            const float a  = aws[pt];
            cw[pt][0] = (1.f - fx) * (1.f - fy) * a;
            cw[pt][1] = fx * (1.f - fy) * a;
            cw[pt][2] = (1.f - fx) * fy * a;
            cw[pt][3] = fx * fy * a;
        }

        const int xmin = min(min(x0[0], x0[1]), min(x0[2], x0[3]));
        const int ymin = min(min(y0[0], y0[1]), min(y0[2], y0[3]));
        const int xmax = max(max(x0[0], x0[1]), max(x0[2], x0[3]));
        const int ymax = max(max(y0[0], y0[1]), max(y0[2], y0[3]));

        if (xmax - xmin <= 2 && ymax - ymin <= 2) {
            // Fast path: all 16 corners live in a 4x4 window. Lane i holds the
            // accumulated weight of cell i (cell = dy*4 + dx).
            float myw = 0.f;
#pragma unroll
            for (int pt = 0; pt < NP; pt++) {
                const int b = (y0[pt] - ymin) * 4 + (x0[pt] - xmin);
                myw += (lane == b)     ? cw[pt][0] : 0.f;
                myw += (lane == b + 1) ? cw[pt][1] : 0.f;
                myw += (lane == b + 4) ? cw[pt][2] : 0.f;
                myw += (lane == b + 5) ? cw[pt][3] : 0.f;
            }
            unsigned nz = __ballot_sync(0xffffffffu, (lane < 16) && (myw != 0.f));
            while (nz) {
                const int cell = __ffs(nz) - 1;
                nz &= nz - 1;
                const float w = __shfl_sync(0xffffffffu, myw, cell);
                const int xx = xmin + (cell & 3);
                const int yy = ymin + (cell >> 2);
                if ((unsigned)xx < (unsigned)Ws && (unsigned)yy < (unsigned)Hs)
                    GATHER(xx, yy, w);
            }
        } else {
            // Rare fallback: per-point corner loads.
#pragma unroll
            for (int pt = 0; pt < NP; pt++) {
                const int xs[2] = {x0[pt], x0[pt] + 1};
                const int ys[2] = {y0[pt], y0[pt] + 1};
#pragma unroll
                for (int cy = 0; cy < 2; cy++) {
#pragma unroll
                    for (int cx = 0; cx < 2; cx++) {
                        const int xx = xs[cx];
                        const int yy = ys[cy];
                        const float w = cw[pt][cy * 2 + cx];
                        if ((unsigned)xx < (unsigned)Ws && (unsigned)yy < (unsigned)Hs)
                            GATHER(xx, yy, w);
                    }
                }
            }
        }
        loff += (size_t)Hs * (size_t)Ws * CCH;
    }
#undef GATHER

    float4* op = (float4*)(out + (size_t)q * CCH);
    op[lane]      = acc0;   // channels [4*lane, 4*lane+4)
    op[32 + lane] = acc1;   // channels [128+4*lane, ...)
}

extern "C" void kernel_launch(void* const* d_in, const int* in_sizes, int n_in,
                              void* d_out, int out_size)
{
    const float* query   = (const float*)d_in[0];
    // d_in[1] = key (unused)
    const float* value   = (const float*)d_in[2];
    const float* refpts  = (const float*)d_in[3];
    const int*   shapes  = (const int*)d_in[4];
    const float* W_off   = (const float*)d_in[5];
    const float* b_off   = (const float*)d_in[6];
    const float* W_attn  = (const float*)d_in[7];
    const float* b_attn  = (const float*)d_in[8];
    float*       out     = (float*)d_out;

    const int Q = in_sizes[0] / CCH;

    proj_kernel<<<(Q + 127) / 128, 256>>>(query, W_off, b_off, W_attn, b_attn, Q);
    sample_kernel<<<(Q + WPB - 1) / WPB, WPB * 32>>>(value, refpts, shapes, out, Q);
}

// round 10
// speedup vs baseline: 1.6640x; 1.0570x over previous
#include <cuda_runtime.h>
#include <cuda_bf16.h>

#define CCH 256        // channels
#define LV 2           // levels
#define NP 4           // points
#define NOFF 16        // offset outputs (LV*NP*2)
#define NAW 8          // attn outputs (LV*NP)
#define NOUT 24        // total projection outputs
#define WPB 8          // warps per block (sampling kernel)
#define NKT 32         // k-tiles (256 / 8)
#define NNT 3          // n-tiles (24 / 8)
#define K1_WARPS 4     // proj warps per block (64 queries/block)

// Scratch: per-query projection results {16 raw offsets, 8 normalized attn w}.
__device__ float g_P[1 << 21];   // 8.4 MB, supports Q up to ~87k

__device__ __forceinline__ unsigned f2tf32(float f) {
    unsigned r;
    asm("cvt.rna.tf32.f32 %0, %1;" : "=r"(r) : "f"(f));
    return r;
}

__device__ __forceinline__ void mma_tf32(float d[4],
                                         unsigned a0, unsigned a1,
                                         unsigned a2, unsigned a3,
                                         unsigned b0, unsigned b1) {
    asm("mma.sync.aligned.m16n8k8.row.col.f32.tf32.tf32.f32 "
        "{%0,%1,%2,%3}, {%4,%5,%6,%7}, {%8,%9}, {%0,%1,%2,%3};"
        : "+f"(d[0]), "+f"(d[1]), "+f"(d[2]), "+f"(d[3])
        : "r"(a0), "r"(a1), "r"(a2), "r"(a3), "r"(b0), "r"(b1));
}

// ---------------------------------------------------------------------------
// Kernel 1: projection + softmax via tf32 MMA, permuted-k A loads.
// Lane (g,t) loads full float4s of rows g / g+8 (100% sector efficiency);
// B is staged with the matching k-permutation so fragments pair correctly:
// for MMA i of a 4-tile group, b0(t) = W[32*kt4 + 4t + i][n], b1 = +16.
// ---------------------------------------------------------------------------
__global__ __launch_bounds__(K1_WARPS * 32)
void proj_kernel(const float* __restrict__ query,
                 const float* __restrict__ W_off,  const float* __restrict__ b_off,
                 const float* __restrict__ W_attn, const float* __restrict__ b_attn,
                 int Q)
{
    __shared__ unsigned b0sm[NKT * NNT * 32];     // 12KB
    __shared__ unsigned b1sm[NKT * NNT * 32];     // 12KB
    __shared__ float    csm[K1_WARPS][16][28];    // 7KB epilogue staging

    for (int idx = threadIdx.x; idx < NKT * NNT * 32; idx += K1_WARPS * 32) {
        const int ln   = idx & 31;
        const int pair = idx >> 5;
        const int kt   = pair / 3;
        const int nt   = pair - kt * 3;
        const int tig  = ln & 3;
        const int gid  = ln >> 2;
        const int n    = nt * 8 + gid;
        // permuted k: group kt4 = kt>>2, mma i = kt&3
        const int k0   = 32 * (kt >> 2) + 4 * tig + (kt & 3);
        const int k1   = k0 + 16;
        float w0, w1;
        if (n < NOFF) {
            w0 = __ldg(W_off + k0 * NOFF + n);
            w1 = __ldg(W_off + k1 * NOFF + n);
        } else {
            w0 = __ldg(W_attn + k0 * NAW + (n - NOFF));
            w1 = __ldg(W_attn + k1 * NAW + (n - NOFF));
        }
        b0sm[idx] = f2tf32(w0);
        b1sm[idx] = f2tf32(w1);
    }
    __syncthreads();

    const int tid  = threadIdx.x;
    const int lane = tid & 31;
    const int warp = tid >> 5;
    const int gid  = lane >> 2;     // row within 8
    const int tig  = lane & 3;      // thread-in-group

    const int qbase = blockIdx.x * (K1_WARPS * 16) + warp * 16;
    const int qr0 = min(qbase + gid,     Q - 1);   // clamp loads
    const int qr1 = min(qbase + gid + 8, Q - 1);
    const float4* q0p = (const float4*)(query + (size_t)qr0 * CCH) + tig;
    const float4* q1p = (const float4*)(query + (size_t)qr1 * CCH) + tig;

    float d[NNT][4];
#pragma unroll
    for (int nt = 0; nt < NNT; nt++)
#pragma unroll
        for (int i = 0; i < 4; i++) d[nt][i] = 0.f;

#pragma unroll
    for (int kt4 = 0; kt4 < NKT / 4; kt4++) {
        // 4 independent LDG.128; each warp-wide load = 16 rows x 64B packed.
        const float4 r0lo = __ldg(q0p + kt4 * 8);
        const float4 r0hi = __ldg(q0p + kt4 * 8 + 4);
        const float4 r1lo = __ldg(q1p + kt4 * 8);
        const float4 r1hi = __ldg(q1p + kt4 * 8 + 4);
        const int base = (kt4 * 4) * (NNT * 32) + lane;

#define PSTEP(I, C)                                                            \
        do {                                                                   \
            const unsigned a0 = f2tf32(r0lo.C);                                \
            const unsigned a1 = f2tf32(r1lo.C);                                \
            const unsigned a2 = f2tf32(r0hi.C);                                \
            const unsigned a3 = f2tf32(r1hi.C);                                \
            const int bb = base + I * (NNT * 32);                              \
            mma_tf32(d[0], a0, a1, a2, a3, b0sm[bb],      b1sm[bb]);           \
            mma_tf32(d[1], a0, a1, a2, a3, b0sm[bb + 32], b1sm[bb + 32]);      \
            mma_tf32(d[2], a0, a1, a2, a3, b0sm[bb + 64], b1sm[bb + 64]);      \
        } while (0)

        PSTEP(0, x);
        PSTEP(1, y);
        PSTEP(2, z);
        PSTEP(3, w);
#undef PSTEP
    }

    // Scatter C fragments to smem: c0/c1 -> row gid, c2/c3 -> row gid+8.
#pragma unroll
    for (int nt = 0; nt < NNT; nt++) {
        const int col = nt * 8 + 2 * tig;
        csm[warp][gid][col]         = d[nt][0];
        csm[warp][gid][col + 1]     = d[nt][1];
        csm[warp][gid + 8][col]     = d[nt][2];
        csm[warp][gid + 8][col + 1] = d[nt][3];
    }
    __syncwarp();

    if (lane < 16) {
        const int q = qbase + lane;
        if (q < Q) {
            float p[NOUT];
#pragma unroll
            for (int j = 0; j < NOUT; j++) p[j] = csm[warp][lane][j];
#pragma unroll
            for (int j = 0; j < NOFF; j++) p[j] += __ldg(b_off + j);
#pragma unroll
            for (int j = 0; j < NAW; j++)  p[NOFF + j] += __ldg(b_attn + j);

            float m = p[NOFF];
#pragma unroll
            for (int j = 1; j < NAW; j++) m = fmaxf(m, p[NOFF + j]);
            float s = 0.f;
#pragma unroll
            for (int j = 0; j < NAW; j++) {
                const float e = __expf(p[NOFF + j] - m);
                p[NOFF + j] = e;
                s += e;
            }
            const float inv = 1.f / s;
#pragma unroll
            for (int j = 0; j < NAW; j++) p[NOFF + j] *= inv;

            float4* o4 = (float4*)(g_P + (size_t)q * NOUT);
#pragma unroll
            for (int i = 0; i < 6; i++)
                o4[i] = make_float4(p[4 * i], p[4 * i + 1],
                                    p[4 * i + 2], p[4 * i + 3]);
        }
    }
}

// ---------------------------------------------------------------------------
// Kernel 2: bilinear sampling with corner deduplication.  warp = query.
// (unchanged — proven at 57.0us)
// ---------------------------------------------------------------------------
__global__ __launch_bounds__(WPB * 32, 6)
void sample_kernel(const float* __restrict__ value,
                   const float* __restrict__ refpts,
                   const int*   __restrict__ shapes_raw,
                   float* __restrict__ out, int Q)
{
    const int tid  = threadIdx.x;
    const int lane = tid & 31;
    const int q = blockIdx.x * WPB + (tid >> 5);
    if (q >= Q) return;

    // decode spatial shapes (int64 little-endian -> odd int32 slots are 0)
    int HH[LV], WW[LV];
    {
        const int st = (__ldg(shapes_raw + 1) == 0) ? 2 : 1;
#pragma unroll
        for (int l = 0; l < LV; l++) {
            HH[l] = __ldg(shapes_raw + (2 * l) * st);
            WW[l] = __ldg(shapes_raw + (2 * l + 1) * st);
        }
    }

    const float4* pf  = (const float4*)(g_P + (size_t)q * NOUT);
    const float*  ref = refpts + (size_t)q * (LV * 2);

    float4 acc0 = make_float4(0.f, 0.f, 0.f, 0.f);
    float4 acc1 = make_float4(0.f, 0.f, 0.f, 0.f);
    size_t loff = 0;

#define GATHER(XX, YY, W)                                                      \
    do {                                                                       \
        const unsigned off4 = (((unsigned)(YY) * (unsigned)Ws + (unsigned)(XX)) << 6); \
        const float4 v0 = __ldg(vb4 + off4 + lane);                            \
        const float4 v1 = __ldg(vb4 + off4 + 32 + lane);                       \
        acc0.x = fmaf((W), v0.x, acc0.x);                                      \
        acc0.y = fmaf((W), v0.y, acc0.y);                                      \
        acc0.z = fmaf((W), v0.z, acc0.z);                                      \
        acc0.w = fmaf((W), v0.w, acc0.w);                                      \
        acc1.x = fmaf((W), v1.x, acc1.x);                                      \
        acc1.y = fmaf((W), v1.y, acc1.y);                                      \
        acc1.z = fmaf((W), v1.z, acc1.z);                                      \
        acc1.w = fmaf((W), v1.w, acc1.w);                                      \
    } while (0)

#pragma unroll
    for (int l = 0; l < LV; l++) {
        const int Hs = HH[l], Ws = WW[l];
        // ix = (rx + ox/W)*W - 0.5 == rx*W + ox - 0.5
        const float bx = __ldg(ref + 2 * l)     * (float)Ws - 0.5f;
        const float by = __ldg(ref + 2 * l + 1) * (float)Hs - 0.5f;

        const float4 o0 = __ldg(pf + 2 * l);       // offsets pts 0,1 (x,y,x,y)
        const float4 o1 = __ldg(pf + 2 * l + 1);   // offsets pts 2,3
        const float4 wv = __ldg(pf + 4 + l);       // 4 normalized attn weights
        const float4* vb4 = (const float4*)(value + loff);

        const float oxs[NP] = {o0.x, o0.z, o1.x, o1.z};
        const float oys[NP] = {o0.y, o0.w, o1.y, o1.w};
        const float aws[NP] = {wv.x, wv.y, wv.z, wv.w};

        int   x0[NP], y0[NP];
        float cw[NP][4];   // w00, w01, w10, w11 per point
#pragma unroll
        for (int pt = 0; pt < NP; pt++) {
            const float ix = bx + oxs[pt];
            const float iy = by + oys[pt];
            const float x0f = floorf(ix);
            const float y0f = floorf(iy);
            x0[pt] = (int)x0f;
            y0[pt] = (int)y0f;
            const float fx = ix - x0f;
            const float fy = iy - y0f;
            const float a  = aws[pt];
            cw[pt][0] = (1.f - fx) * (1.f - fy) * a;
            cw[pt][1] = fx * (1.f - fy) * a;
            cw[pt][2] = (1.f - fx) * fy * a;
            cw[pt][3] = fx * fy * a;
        }

        const int xmin = min(min(x0[0], x0[1]), min(x0[2], x0[3]));
        const int ymin = min(min(y0[0], y0[1]), min(y0[2], y0[3]));
        const int xmax = max(max(x0[0], x0[1]), max(x0[2], x0[3]));
        const int ymax = max(max(y0[0], y0[1]), max(y0[2], y0[3]));

        if (xmax - xmin <= 2 && ymax - ymin <= 2) {
            // Fast path: all 16 corners live in a 4x4 window. Lane i holds the
            // accumulated weight of cell i (cell = dy*4 + dx).
            float myw = 0.f;
#pragma unroll
            for (int pt = 0; pt < NP; pt++) {
                const int b = (y0[pt] - ymin) * 4 + (x0[pt] - xmin);
                myw += (lane == b)     ? cw[pt][0] : 0.f;
                myw += (lane == b + 1) ? cw[pt][1] : 0.f;
                myw += (lane == b + 4) ? cw[pt][2] : 0.f;
                myw += (lane == b + 5) ? cw[pt][3] : 0.f;
            }
            unsigned nz = __ballot_sync(0xffffffffu, (lane < 16) && (myw != 0.f));
            while (nz) {
                const int cell = __ffs(nz) - 1;
                nz &= nz - 1;
                const float w = __shfl_sync(0xffffffffu, myw, cell);
                const int xx = xmin + (cell & 3);
                const int yy = ymin + (cell >> 2);
                if ((unsigned)xx < (unsigned)Ws && (unsigned)yy < (unsigned)Hs)
                    GATHER(xx, yy, w);
            }
        } else {
            // Rare fallback: per-point corner loads.
#pragma unroll
            for (int pt = 0; pt < NP; pt++) {
                const int xs[2] = {x0[pt], x0[pt] + 1};
                const int ys[2] = {y0[pt], y0[pt] + 1};
#pragma unroll
                for (int cy = 0; cy < 2; cy++) {
#pragma unroll
                    for (int cx = 0; cx < 2; cx++) {
                        const int xx = xs[cx];
                        const int yy = ys[cy];
                        const float w = cw[pt][cy * 2 + cx];
                        if ((unsigned)xx < (unsigned)Ws && (unsigned)yy < (unsigned)Hs)
                            GATHER(xx, yy, w);
                    }
                }
            }
        }
        loff += (size_t)Hs * (size_t)Ws * CCH;
    }
#undef GATHER

    float4* op = (float4*)(out + (size_t)q * CCH);
    op[lane]      = acc0;   // channels [4*lane, 4*lane+4)
    op[32 + lane] = acc1;   // channels [128+4*lane, ...)
}

extern "C" void kernel_launch(void* const* d_in, const int* in_sizes, int n_in,
                              void* d_out, int out_size)
{
    const float* query   = (const float*)d_in[0];
    // d_in[1] = key (unused)
    const float* value   = (const float*)d_in[2];
    const float* refpts  = (const float*)d_in[3];
    const int*   shapes  = (const int*)d_in[4];
    const float* W_off   = (const float*)d_in[5];
    const float* b_off   = (const float*)d_in[6];
    const float* W_attn  = (const float*)d_in[7];
    const float* b_attn  = (const float*)d_in[8];
    float*       out     = (float*)d_out;

    const int Q = in_sizes[0] / CCH;

    const int qpb = K1_WARPS * 16;
    proj_kernel<<<(Q + qpb - 1) / qpb, K1_WARPS * 32>>>(
        query, W_off, b_off, W_attn, b_attn, Q);
    sample_kernel<<<(Q + WPB - 1) / WPB, WPB * 32>>>(
        value, refpts, shapes, out, Q);
}

// round 11
// speedup vs baseline: 1.8642x; 1.1203x over previous
#include <cuda_runtime.h>
#include <cuda_bf16.h>

#define CCH 256        // channels
#define LV 2           // levels
#define NP 4           // points
#define NOFF 16        // offset outputs (LV*NP*2)
#define NAW 8          // attn outputs (LV*NP)
#define NOUT 24        // total projection outputs
#define WPB 8          // warps per block (sampling kernel)
#define NKT 32         // k-tiles (256 / 8)
#define NNT 3          // n-tiles (24 / 8)
#define K1_WARPS 4     // proj warps per block (64 queries/block)

// Scratch: per-query projection results {16 raw offsets, 8 normalized attn w}.
__device__ float g_P[1 << 21];   // 8.4 MB, supports Q up to ~87k

__device__ __forceinline__ unsigned f2tf32(float f) {
    unsigned r;
    asm("cvt.rna.tf32.f32 %0, %1;" : "=r"(r) : "f"(f));
    return r;
}

__device__ __forceinline__ void mma_tf32(float d[4],
                                         unsigned a0, unsigned a1,
                                         unsigned a2, unsigned a3,
                                         unsigned b0, unsigned b1) {
    asm("mma.sync.aligned.m16n8k8.row.col.f32.tf32.tf32.f32 "
        "{%0,%1,%2,%3}, {%4,%5,%6,%7}, {%8,%9}, {%0,%1,%2,%3};"
        : "+f"(d[0]), "+f"(d[1]), "+f"(d[2]), "+f"(d[3])
        : "r"(a0), "r"(a1), "r"(a2), "r"(a3), "r"(b0), "r"(b1));
}

// ---------------------------------------------------------------------------
// Kernel 1: projection + softmax via tf32 MMA, permuted-k A loads.
// (unchanged from round 10 — proven at ~19us)
// ---------------------------------------------------------------------------
__global__ __launch_bounds__(K1_WARPS * 32)
void proj_kernel(const float* __restrict__ query,
                 const float* __restrict__ W_off,  const float* __restrict__ b_off,
                 const float* __restrict__ W_attn, const float* __restrict__ b_attn,
                 int Q)
{
    __shared__ unsigned b0sm[NKT * NNT * 32];     // 12KB
    __shared__ unsigned b1sm[NKT * NNT * 32];     // 12KB
    __shared__ float    csm[K1_WARPS][16][28];    // 7KB epilogue staging

    for (int idx = threadIdx.x; idx < NKT * NNT * 32; idx += K1_WARPS * 32) {
        const int ln   = idx & 31;
        const int pair = idx >> 5;
        const int kt   = pair / 3;
        const int nt   = pair - kt * 3;
        const int tig  = ln & 3;
        const int gid  = ln >> 2;
        const int n    = nt * 8 + gid;
        const int k0   = 32 * (kt >> 2) + 4 * tig + (kt & 3);
        const int k1   = k0 + 16;
        float w0, w1;
        if (n < NOFF) {
            w0 = __ldg(W_off + k0 * NOFF + n);
            w1 = __ldg(W_off + k1 * NOFF + n);
        } else {
            w0 = __ldg(W_attn + k0 * NAW + (n - NOFF));
            w1 = __ldg(W_attn + k1 * NAW + (n - NOFF));
        }
        b0sm[idx] = f2tf32(w0);
        b1sm[idx] = f2tf32(w1);
    }
    __syncthreads();

    const int tid  = threadIdx.x;
    const int lane = tid & 31;
    const int warp = tid >> 5;
    const int gid  = lane >> 2;
    const int tig  = lane & 3;

    const int qbase = blockIdx.x * (K1_WARPS * 16) + warp * 16;
    const int qr0 = min(qbase + gid,     Q - 1);
    const int qr1 = min(qbase + gid + 8, Q - 1);
    const float4* q0p = (const float4*)(query + (size_t)qr0 * CCH) + tig;
    const float4* q1p = (const float4*)(query + (size_t)qr1 * CCH) + tig;

    float d[NNT][4];
#pragma unroll
    for (int nt = 0; nt < NNT; nt++)
#pragma unroll
        for (int i = 0; i < 4; i++) d[nt][i] = 0.f;

#pragma unroll
    for (int kt4 = 0; kt4 < NKT / 4; kt4++) {
        const float4 r0lo = __ldg(q0p + kt4 * 8);
        const float4 r0hi = __ldg(q0p + kt4 * 8 + 4);
        const float4 r1lo = __ldg(q1p + kt4 * 8);
        const float4 r1hi = __ldg(q1p + kt4 * 8 + 4);
        const int base = (kt4 * 4) * (NNT * 32) + lane;

#define PSTEP(I, C)                                                            \
        do {                                                                   \
            const unsigned a0 = f2tf32(r0lo.C);                                \
            const unsigned a1 = f2tf32(r1lo.C);                                \
            const unsigned a2 = f2tf32(r0hi.C);                                \
            const unsigned a3 = f2tf32(r1hi.C);                                \
            const int bb = base + I * (NNT * 32);                              \
            mma_tf32(d[0], a0, a1, a2, a3, b0sm[bb],      b1sm[bb]);           \
            mma_tf32(d[1], a0, a1, a2, a3, b0sm[bb + 32], b1sm[bb + 32]);      \
            mma_tf32(d[2], a0, a1, a2, a3, b0sm[bb + 64], b1sm[bb + 64]);      \
        } while (0)

        PSTEP(0, x);
        PSTEP(1, y);
        PSTEP(2, z);
        PSTEP(3, w);
#undef PSTEP
    }

#pragma unroll
    for (int nt = 0; nt < NNT; nt++) {
        const int col = nt * 8 + 2 * tig;
        csm[warp][gid][col]         = d[nt][0];
        csm[warp][gid][col + 1]     = d[nt][1];
        csm[warp][gid + 8][col]     = d[nt][2];
        csm[warp][gid + 8][col + 1] = d[nt][3];
    }
    __syncwarp();

    if (lane < 16) {
        const int q = qbase + lane;
        if (q < Q) {
            float p[NOUT];
#pragma unroll
            for (int j = 0; j < NOUT; j++) p[j] = csm[warp][lane][j];
#pragma unroll
            for (int j = 0; j < NOFF; j++) p[j] += __ldg(b_off + j);
#pragma unroll
            for (int j = 0; j < NAW; j++)  p[NOFF + j] += __ldg(b_attn + j);

            float m = p[NOFF];
#pragma unroll
            for (int j = 1; j < NAW; j++) m = fmaxf(m, p[NOFF + j]);
            float s = 0.f;
#pragma unroll
            for (int j = 0; j < NAW; j++) {
                const float e = __expf(p[NOFF + j] - m);
                p[NOFF + j] = e;
                s += e;
            }
            const float inv = 1.f / s;
#pragma unroll
            for (int j = 0; j < NAW; j++) p[NOFF + j] *= inv;

            float4* o4 = (float4*)(g_P + (size_t)q * NOUT);
#pragma unroll
            for (int i = 0; i < 6; i++)
                o4[i] = make_float4(p[4 * i], p[4 * i + 1],
                                    p[4 * i + 2], p[4 * i + 3]);
        }
    }
}

// ---------------------------------------------------------------------------
// Kernel 2: bilinear sampling.  warp = query.
// Merged-level dedup: lane 0-15 owns level-0 cell (lane), lane 16-31 owns
// level-1 cell (lane-16).  Per-lane weight (bounds folded in) + clamped
// address precomputed; one ballot; gather loop processes 4 cells/iteration
// with all 8 LDG.128 issued back-to-back -> ~3 latency exposures per query
// instead of ~10.
// ---------------------------------------------------------------------------
__global__ __launch_bounds__(WPB * 32, 5)
void sample_kernel(const float* __restrict__ value,
                   const float* __restrict__ refpts,
                   const int*   __restrict__ shapes_raw,
                   float* __restrict__ out, int Q)
{
    const int tid  = threadIdx.x;
    const int lane = tid & 31;
    const int q = blockIdx.x * WPB + (tid >> 5);
    if (q >= Q) return;

    // decode spatial shapes (int64 little-endian -> odd int32 slots are 0)
    int HH[LV], WW[LV];
    {
        const int st = (__ldg(shapes_raw + 1) == 0) ? 2 : 1;
#pragma unroll
        for (int l = 0; l < LV; l++) {
            HH[l] = __ldg(shapes_raw + (2 * l) * st);
            WW[l] = __ldg(shapes_raw + (2 * l + 1) * st);
        }
    }

    const float4* pf  = (const float4*)(g_P + (size_t)q * NOUT);
    const float*  ref = refpts + (size_t)q * (LV * 2);
    const float4* vb4 = (const float4*)value;

    float4 acc0 = make_float4(0.f, 0.f, 0.f, 0.f);
    float4 acc1 = make_float4(0.f, 0.f, 0.f, 0.f);

    float    myw   = 0.f;     // weight of the cell this lane owns
    unsigned myoff = 0;       // float4-offset of that cell (clamped, safe)
    const int mylevel = lane >> 4;
    const int mycell  = lane & 15;

    unsigned loff4 = 0;       // level base offset in float4 units

#define GATHER_NOW(OFF4, W)                                                    \
    do {                                                                       \
        const float4 v0 = __ldg(vb4 + (OFF4) + lane);                          \
        const float4 v1 = __ldg(vb4 + (OFF4) + 32 + lane);                     \
        acc0.x = fmaf((W), v0.x, acc0.x);                                      \
        acc0.y = fmaf((W), v0.y, acc0.y);                                      \
        acc0.z = fmaf((W), v0.z, acc0.z);                                      \
        acc0.w = fmaf((W), v0.w, acc0.w);                                      \
        acc1.x = fmaf((W), v1.x, acc1.x);                                      \
        acc1.y = fmaf((W), v1.y, acc1.y);                                      \
        acc1.z = fmaf((W), v1.z, acc1.z);                                      \
        acc1.w = fmaf((W), v1.w, acc1.w);                                      \
    } while (0)

#pragma unroll
    for (int l = 0; l < LV; l++) {
        const int Hs = HH[l], Ws = WW[l];
        const float bx = __ldg(ref + 2 * l)     * (float)Ws - 0.5f;
        const float by = __ldg(ref + 2 * l + 1) * (float)Hs - 0.5f;

        const float4 oA = __ldg(pf + 2 * l);
        const float4 oB = __ldg(pf + 2 * l + 1);
        const float4 wv = __ldg(pf + 4 + l);

        const float oxs[NP] = {oA.x, oA.z, oB.x, oB.z};
        const float oys[NP] = {oA.y, oA.w, oB.y, oB.w};
        const float aws[NP] = {wv.x, wv.y, wv.z, wv.w};

        int   x0[NP], y0[NP];
        float cw[NP][4];
#pragma unroll
        for (int pt = 0; pt < NP; pt++) {
            const float ix = bx + oxs[pt];
            const float iy = by + oys[pt];
            const float x0f = floorf(ix);
            const float y0f = floorf(iy);
            x0[pt] = (int)x0f;
            y0[pt] = (int)y0f;
            const float fx = ix - x0f;
            const float fy = iy - y0f;
            const float a  = aws[pt];
            cw[pt][0] = (1.f - fx) * (1.f - fy) * a;
            cw[pt][1] = fx * (1.f - fy) * a;
            cw[pt][2] = (1.f - fx) * fy * a;
            cw[pt][3] = fx * fy * a;
        }

        const int xmin = min(min(x0[0], x0[1]), min(x0[2], x0[3]));
        const int ymin = min(min(y0[0], y0[1]), min(y0[2], y0[3]));
        const int xmax = max(max(x0[0], x0[1]), max(x0[2], x0[3]));
        const int ymax = max(max(y0[0], y0[1]), max(y0[2], y0[3]));

        if (xmax - xmin <= 2 && ymax - ymin <= 2) {
            // Fast path: this level's 16 corners live in a 4x4 window.
            if (mylevel == l) {
                const int xx = xmin + (mycell & 3);
                const int yy = ymin + (mycell >> 2);
                float w = 0.f;
#pragma unroll
                for (int pt = 0; pt < NP; pt++) {
                    const int b = (y0[pt] - ymin) * 4 + (x0[pt] - xmin);
                    w += (mycell == b)     ? cw[pt][0] : 0.f;
                    w += (mycell == b + 1) ? cw[pt][1] : 0.f;
                    w += (mycell == b + 4) ? cw[pt][2] : 0.f;
                    w += (mycell == b + 5) ? cw[pt][3] : 0.f;
                }
                const bool ok = (unsigned)xx < (unsigned)Ws &&
                                (unsigned)yy < (unsigned)Hs;
                myw = ok ? w : 0.f;
                const int xc = min(max(xx, 0), Ws - 1);
                const int yc = min(max(yy, 0), Hs - 1);
                myoff = loff4 + (((unsigned)(yc * Ws + xc)) << 6);
            }
        } else {
            // Rare fallback: immediate per-corner gathers for this level.
#pragma unroll
            for (int pt = 0; pt < NP; pt++) {
                const int xs[2] = {x0[pt], x0[pt] + 1};
                const int ys[2] = {y0[pt], y0[pt] + 1};
#pragma unroll
                for (int cy = 0; cy < 2; cy++) {
#pragma unroll
                    for (int cx = 0; cx < 2; cx++) {
                        const int xx = xs[cx];
                        const int yy = ys[cy];
                        const float w = cw[pt][cy * 2 + cx];
                        if ((unsigned)xx < (unsigned)Ws && (unsigned)yy < (unsigned)Hs) {
                            const unsigned off4 =
                                loff4 + (((unsigned)(yy * Ws + xx)) << 6);
                            GATHER_NOW(off4, w);
                        }
                    }
                }
            }
        }
        loff4 += (unsigned)(Hs * Ws) * 64u;
    }

    // Merged gather loop: 4 cells per iteration, loads batched.
    unsigned nz = __ballot_sync(0xffffffffu, myw != 0.f);
    while (nz) {
        int c0 = __ffs(nz) - 1; nz &= nz - 1;
        int c1 = __ffs(nz) - 1; nz &= nz - 1;
        int c2 = __ffs(nz) - 1; nz &= nz - 1;
        int c3 = __ffs(nz) - 1; nz &= nz - 1;

        float    w0 = __shfl_sync(0xffffffffu, myw,   c0 & 31);
        unsigned f0 = __shfl_sync(0xffffffffu, myoff, c0 & 31);
        float    w1 = __shfl_sync(0xffffffffu, myw,   c1 & 31);
        unsigned f1 = __shfl_sync(0xffffffffu, myoff, c1 & 31);
        float    w2 = __shfl_sync(0xffffffffu, myw,   c2 & 31);
        unsigned f2 = __shfl_sync(0xffffffffu, myoff, c2 & 31);
        float    w3 = __shfl_sync(0xffffffffu, myw,   c3 & 31);
        unsigned f3 = __shfl_sync(0xffffffffu, myoff, c3 & 31);
        if (c1 < 0) w1 = 0.f;
        if (c2 < 0) w2 = 0.f;
        if (c3 < 0) w3 = 0.f;

        float4 a0 = make_float4(0.f,0.f,0.f,0.f), b0 = a0;
        float4 a1 = a0, b1 = a0, a2 = a0, b2 = a0, a3 = a0, b3 = a0;
        // c0 always valid; batch all loads back-to-back.
        a0 = __ldg(vb4 + f0 + lane);
        b0 = __ldg(vb4 + f0 + 32 + lane);
        if (c1 >= 0) { a1 = __ldg(vb4 + f1 + lane); b1 = __ldg(vb4 + f1 + 32 + lane); }
        if (c2 >= 0) { a2 = __ldg(vb4 + f2 + lane); b2 = __ldg(vb4 + f2 + 32 + lane); }
        if (c3 >= 0) { a3 = __ldg(vb4 + f3 + lane); b3 = __ldg(vb4 + f3 + 32 + lane); }

        acc0.x = fmaf(w0, a0.x, acc0.x); acc0.y = fmaf(w0, a0.y, acc0.y);
        acc0.z = fmaf(w0, a0.z, acc0.z); acc0.w = fmaf(w0, a0.w, acc0.w);
        acc1.x = fmaf(w0, b0.x, acc1.x); acc1.y = fmaf(w0, b0.y, acc1.y);
        acc1.z = fmaf(w0, b0.z, acc1.z); acc1.w = fmaf(w0, b0.w, acc1.w);

        acc0.x = fmaf(w1, a1.x, acc0.x); acc0.y = fmaf(w1, a1.y, acc0.y);
        acc0.z = fmaf(w1, a1.z, acc0.z); acc0.w = fmaf(w1, a1.w, acc0.w);
        acc1.x = fmaf(w1, b1.x, acc1.x); acc1.y = fmaf(w1, b1.y, acc1.y);
        acc1.z = fmaf(w1, b1.z, acc1.z); acc1.w = fmaf(w1, b1.w, acc1.w);

        acc0.x = fmaf(w2, a2.x, acc0.x); acc0.y = fmaf(w2, a2.y, acc0.y);
        acc0.z = fmaf(w2, a2.z, acc0.z); acc0.w = fmaf(w2, a2.w, acc0.w);
        acc1.x = fmaf(w2, b2.x, acc1.x); acc1.y = fmaf(w2, b2.y, acc1.y);
        acc1.z = fmaf(w2, b2.z, acc1.z); acc1.w = fmaf(w2, b2.w, acc1.w);

        acc0.x = fmaf(w3, a3.x, acc0.x); acc0.y = fmaf(w3, a3.y, acc0.y);
        acc0.z = fmaf(w3, a3.z, acc0.z); acc0.w = fmaf(w3, a3.w, acc0.w);
        acc1.x = fmaf(w3, b3.x, acc1.x); acc1.y = fmaf(w3, b3.y, acc1.y);
        acc1.z = fmaf(w3, b3.z, acc1.z); acc1.w = fmaf(w3, b3.w, acc1.w);
    }
#undef GATHER_NOW

    float4* op = (float4*)(out + (size_t)q * CCH);
    op[lane]      = acc0;   // channels [4*lane, 4*lane+4)
    op[32 + lane] = acc1;   // channels [128+4*lane, ...)
}

extern "C" void kernel_launch(void* const* d_in, const int* in_sizes, int n_in,
                              void* d_out, int out_size)
{
    const float* query   = (const float*)d_in[0];
    // d_in[1] = key (unused)
    const float* value   = (const float*)d_in[2];
    const float* refpts  = (const float*)d_in[3];
    const int*   shapes  = (const int*)d_in[4];
    const float* W_off   = (const float*)d_in[5];
    const float* b_off   = (const float*)d_in[6];
    const float* W_attn  = (const float*)d_in[7];
    const float* b_attn  = (const float*)d_in[8];
    float*       out     = (float*)d_out;

    const int Q = in_sizes[0] / CCH;

    const int qpb = K1_WARPS * 16;
    proj_kernel<<<(Q + qpb - 1) / qpb, K1_WARPS * 32>>>(
        query, W_off, b_off, W_attn, b_attn, Q);
    sample_kernel<<<(Q + WPB - 1) / WPB, WPB * 32>>>(
        value, refpts, shapes, out, Q);
}

// round 12
// speedup vs baseline: 1.9361x; 1.0386x over previous
#include <cuda_runtime.h>
#include <cuda_bf16.h>

#define CCH 256        // channels
#define LV 2           // levels
#define NP 4           // points
#define NOFF 16        // offset outputs (LV*NP*2)
#define NAW 8          // attn outputs (LV*NP)
#define NOUT 24        // total projection outputs
#define WPB 8          // warps per block (sampling kernel)
#define NKT 32         // k-tiles (256 / 8)
#define NNT 3          // n-tiles (24 / 8)
#define K1_WARPS 4     // proj warps per block (64 queries/block)

// Scratch: per-query projection results {16 raw offsets, 8 normalized attn w}.
__device__ float g_P[1 << 21];   // 8.4 MB, supports Q up to ~87k

__device__ __forceinline__ unsigned f2tf32(float f) {
    unsigned r;
    asm("cvt.rna.tf32.f32 %0, %1;" : "=r"(r) : "f"(f));
    return r;
}

__device__ __forceinline__ void mma_tf32(float d[4],
                                         unsigned a0, unsigned a1,
                                         unsigned a2, unsigned a3,
                                         unsigned b0, unsigned b1) {
    asm("mma.sync.aligned.m16n8k8.row.col.f32.tf32.tf32.f32 "
        "{%0,%1,%2,%3}, {%4,%5,%6,%7}, {%8,%9}, {%0,%1,%2,%3};"
        : "+f"(d[0]), "+f"(d[1]), "+f"(d[2]), "+f"(d[3])
        : "r"(a0), "r"(a1), "r"(a2), "r"(a3), "r"(b0), "r"(b1));
}

// ---------------------------------------------------------------------------
// Kernel 1: projection + softmax via tf32 MMA, permuted-k A loads,
// double-buffered query prefetch (loads for kt4+1 issue before MMAs of kt4).
// ---------------------------------------------------------------------------
__global__ __launch_bounds__(K1_WARPS * 32)
void proj_kernel(const float* __restrict__ query,
                 const float* __restrict__ W_off,  const float* __restrict__ b_off,
                 const float* __restrict__ W_attn, const float* __restrict__ b_attn,
                 int Q)
{
    __shared__ unsigned b0sm[NKT * NNT * 32];     // 12KB
    __shared__ unsigned b1sm[NKT * NNT * 32];     // 12KB
    __shared__ float    csm[K1_WARPS][16][28];    // 7KB epilogue staging

    for (int idx = threadIdx.x; idx < NKT * NNT * 32; idx += K1_WARPS * 32) {
        const int ln   = idx & 31;
        const int pair = idx >> 5;
        const int kt   = pair / 3;
        const int nt   = pair - kt * 3;
        const int tig  = ln & 3;
        const int gid  = ln >> 2;
        const int n    = nt * 8 + gid;
        const int k0   = 32 * (kt >> 2) + 4 * tig + (kt & 3);
        const int k1   = k0 + 16;
        float w0, w1;
        if (n < NOFF) {
            w0 = __ldg(W_off + k0 * NOFF + n);
            w1 = __ldg(W_off + k1 * NOFF + n);
        } else {
            w0 = __ldg(W_attn + k0 * NAW + (n - NOFF));
            w1 = __ldg(W_attn + k1 * NAW + (n - NOFF));
        }
        b0sm[idx] = f2tf32(w0);
        b1sm[idx] = f2tf32(w1);
    }
    __syncthreads();

    const int tid  = threadIdx.x;
    const int lane = tid & 31;
    const int warp = tid >> 5;
    const int gid  = lane >> 2;
    const int tig  = lane & 3;

    const int qbase = blockIdx.x * (K1_WARPS * 16) + warp * 16;
    const int qr0 = min(qbase + gid,     Q - 1);
    const int qr1 = min(qbase + gid + 8, Q - 1);
    const float4* q0p = (const float4*)(query + (size_t)qr0 * CCH) + tig;
    const float4* q1p = (const float4*)(query + (size_t)qr1 * CCH) + tig;

    float d[NNT][4];
#pragma unroll
    for (int nt = 0; nt < NNT; nt++)
#pragma unroll
        for (int i = 0; i < 4; i++) d[nt][i] = 0.f;

    float4 r0lo = __ldg(q0p);
    float4 r0hi = __ldg(q0p + 4);
    float4 r1lo = __ldg(q1p);
    float4 r1hi = __ldg(q1p + 4);

#pragma unroll
    for (int kt4 = 0; kt4 < NKT / 4; kt4++) {
        float4 n0lo, n0hi, n1lo, n1hi;
        if (kt4 < NKT / 4 - 1) {          // prefetch next group first
            n0lo = __ldg(q0p + (kt4 + 1) * 8);
            n0hi = __ldg(q0p + (kt4 + 1) * 8 + 4);
            n1lo = __ldg(q1p + (kt4 + 1) * 8);
            n1hi = __ldg(q1p + (kt4 + 1) * 8 + 4);
        }
        const int base = (kt4 * 4) * (NNT * 32) + lane;

#define PSTEP(I, C)                                                            \
        do {                                                                   \
            const unsigned a0 = f2tf32(r0lo.C);                                \
            const unsigned a1 = f2tf32(r1lo.C);                                \
            const unsigned a2 = f2tf32(r0hi.C);                                \
            const unsigned a3 = f2tf32(r1hi.C);                                \
            const int bb = base + I * (NNT * 32);                              \
            mma_tf32(d[0], a0, a1, a2, a3, b0sm[bb],      b1sm[bb]);           \
            mma_tf32(d[1], a0, a1, a2, a3, b0sm[bb + 32], b1sm[bb + 32]);      \
            mma_tf32(d[2], a0, a1, a2, a3, b0sm[bb + 64], b1sm[bb + 64]);      \
        } while (0)

        PSTEP(0, x);
        PSTEP(1, y);
        PSTEP(2, z);
        PSTEP(3, w);
#undef PSTEP

        if (kt4 < NKT / 4 - 1) {
            r0lo = n0lo; r0hi = n0hi; r1lo = n1lo; r1hi = n1hi;
        }
    }

#pragma unroll
    for (int nt = 0; nt < NNT; nt++) {
        const int col = nt * 8 + 2 * tig;
        csm[warp][gid][col]         = d[nt][0];
        csm[warp][gid][col + 1]     = d[nt][1];
        csm[warp][gid + 8][col]     = d[nt][2];
        csm[warp][gid + 8][col + 1] = d[nt][3];
    }
    __syncwarp();

    if (lane < 16) {
        const int q = qbase + lane;
        if (q < Q) {
            float p[NOUT];
#pragma unroll
            for (int j = 0; j < NOUT; j++) p[j] = csm[warp][lane][j];
#pragma unroll
            for (int j = 0; j < NOFF; j++) p[j] += __ldg(b_off + j);
#pragma unroll
            for (int j = 0; j < NAW; j++)  p[NOFF + j] += __ldg(b_attn + j);

            float m = p[NOFF];
#pragma unroll
            for (int j = 1; j < NAW; j++) m = fmaxf(m, p[NOFF + j]);
            float s = 0.f;
#pragma unroll
            for (int j = 0; j < NAW; j++) {
                const float e = __expf(p[NOFF + j] - m);
                p[NOFF + j] = e;
                s += e;
            }
            const float inv = 1.f / s;
#pragma unroll
            for (int j = 0; j < NAW; j++) p[NOFF + j] *= inv;

            float4* o4 = (float4*)(g_P + (size_t)q * NOUT);
#pragma unroll
            for (int i = 0; i < 6; i++)
                o4[i] = make_float4(p[4 * i], p[4 * i + 1],
                                    p[4 * i + 2], p[4 * i + 3]);
        }
    }
}

// ---------------------------------------------------------------------------
// Kernel 2: bilinear sampling.  warp = query.
// Merged-level dedup with tent-function per-lane cell weights:
// weight of integer pixel X for sample ix is max(0, 1-|ix-X|), so lane
// computes its owned cell's total weight in ~7 ops/point instead of the
// cw-table + select chain.  Gather loop: 4 cells/iter, loads batched.
// ---------------------------------------------------------------------------
__global__ __launch_bounds__(WPB * 32, 5)
void sample_kernel(const float* __restrict__ value,
                   const float* __restrict__ refpts,
                   const int*   __restrict__ shapes_raw,
                   float* __restrict__ out, int Q)
{
    const int tid  = threadIdx.x;
    const int lane = tid & 31;
    const int q = blockIdx.x * WPB + (tid >> 5);
    if (q >= Q) return;

    // decode spatial shapes (int64 little-endian -> odd int32 slots are 0)
    int HH[LV], WW[LV];
    {
        const int st = (__ldg(shapes_raw + 1) == 0) ? 2 : 1;
#pragma unroll
        for (int l = 0; l < LV; l++) {
            HH[l] = __ldg(shapes_raw + (2 * l) * st);
            WW[l] = __ldg(shapes_raw + (2 * l + 1) * st);
        }
    }

    const float4* pf  = (const float4*)(g_P + (size_t)q * NOUT);
    const float*  ref = refpts + (size_t)q * (LV * 2);
    const float4* vb4 = (const float4*)value;

    float4 acc0 = make_float4(0.f, 0.f, 0.f, 0.f);
    float4 acc1 = make_float4(0.f, 0.f, 0.f, 0.f);

    float    myw   = 0.f;     // weight of the cell this lane owns
    unsigned myoff = 0;       // float4-offset of that cell (clamped, safe)
    const int mylevel = lane >> 4;
    const int mycell  = lane & 15;

    unsigned loff4 = 0;       // level base offset in float4 units

#define GATHER_NOW(OFF4, W)                                                    \
    do {                                                                       \
        const float4 v0 = __ldg(vb4 + (OFF4) + lane);                          \
        const float4 v1 = __ldg(vb4 + (OFF4) + 32 + lane);                     \
        acc0.x = fmaf((W), v0.x, acc0.x);                                      \
        acc0.y = fmaf((W), v0.y, acc0.y);                                      \
        acc0.z = fmaf((W), v0.z, acc0.z);                                      \
        acc0.w = fmaf((W), v0.w, acc0.w);                                      \
        acc1.x = fmaf((W), v1.x, acc1.x);                                      \
        acc1.y = fmaf((W), v1.y, acc1.y);                                      \
        acc1.z = fmaf((W), v1.z, acc1.z);                                      \
        acc1.w = fmaf((W), v1.w, acc1.w);                                      \
    } while (0)

#pragma unroll
    for (int l = 0; l < LV; l++) {
        const int Hs = HH[l], Ws = WW[l];
        const float bx = __ldg(ref + 2 * l)     * (float)Ws - 0.5f;
        const float by = __ldg(ref + 2 * l + 1) * (float)Hs - 0.5f;

        const float4 oA = __ldg(pf + 2 * l);
        const float4 oB = __ldg(pf + 2 * l + 1);
        const float4 wv = __ldg(pf + 4 + l);

        const float ixs[NP] = {bx + oA.x, bx + oA.z, bx + oB.x, bx + oB.z};
        const float iys[NP] = {by + oA.y, by + oA.w, by + oB.y, by + oB.w};
        const float aws[NP] = {wv.x, wv.y, wv.z, wv.w};

        int x0[NP], y0[NP];
#pragma unroll
        for (int pt = 0; pt < NP; pt++) {
            x0[pt] = (int)floorf(ixs[pt]);
            y0[pt] = (int)floorf(iys[pt]);
        }

        const int xmin = min(min(x0[0], x0[1]), min(x0[2], x0[3]));
        const int ymin = min(min(y0[0], y0[1]), min(y0[2], y0[3]));
        const int xmax = max(max(x0[0], x0[1]), max(x0[2], x0[3]));
        const int ymax = max(max(y0[0], y0[1]), max(y0[2], y0[3]));

        if (xmax - xmin <= 2 && ymax - ymin <= 2) {
            // Fast path: this level's 16 corners live in a 4x4 window.
            if (mylevel == l) {
                const int xx = xmin + (mycell & 3);
                const int yy = ymin + (mycell >> 2);
                const float Xc = (float)xx;
                const float Yc = (float)yy;
                float w = 0.f;
#pragma unroll
                for (int pt = 0; pt < NP; pt++) {
                    const float wx = fmaxf(0.f, 1.f - fabsf(ixs[pt] - Xc));
                    const float wy = fmaxf(0.f, 1.f - fabsf(iys[pt] - Yc));
                    w = fmaf(aws[pt] * wx, wy, w);
                }
                const bool ok = (unsigned)xx < (unsigned)Ws &&
                                (unsigned)yy < (unsigned)Hs;
                myw = ok ? w : 0.f;
                const int xc = min(max(xx, 0), Ws - 1);
                const int yc = min(max(yy, 0), Hs - 1);
                myoff = loff4 + (((unsigned)(yc * Ws + xc)) << 6);
            }
        } else {
            // Rare fallback: immediate per-corner gathers for this level.
#pragma unroll
            for (int pt = 0; pt < NP; pt++) {
                const float x0f = floorf(ixs[pt]);
                const float y0f = floorf(iys[pt]);
                const float fx = ixs[pt] - x0f;
                const float fy = iys[pt] - y0f;
                const float a  = aws[pt];
                const float cw[4] = {(1.f - fx) * (1.f - fy) * a,
                                     fx * (1.f - fy) * a,
                                     (1.f - fx) * fy * a,
                                     fx * fy * a};
                const int xs[2] = {x0[pt], x0[pt] + 1};
                const int ys[2] = {y0[pt], y0[pt] + 1};
#pragma unroll
                for (int cy = 0; cy < 2; cy++) {
#pragma unroll
                    for (int cx = 0; cx < 2; cx++) {
                        const int xx = xs[cx];
                        const int yy = ys[cy];
                        const float w = cw[cy * 2 + cx];
                        if ((unsigned)xx < (unsigned)Ws && (unsigned)yy < (unsigned)Hs) {
                            const unsigned off4 =
                                loff4 + (((unsigned)(yy * Ws + xx)) << 6);
                            GATHER_NOW(off4, w);
                        }
                    }
                }
            }
        }
        loff4 += (unsigned)(Hs * Ws) * 64u;
    }

    // Merged gather loop: 4 cells per iteration, loads batched.
    unsigned nz = __ballot_sync(0xffffffffu, myw != 0.f);
    while (nz) {
        int c0 = __ffs(nz) - 1; nz &= nz - 1;
        int c1 = __ffs(nz) - 1; nz &= nz - 1;
        int c2 = __ffs(nz) - 1; nz &= nz - 1;
        int c3 = __ffs(nz) - 1; nz &= nz - 1;

        float    w0 = __shfl_sync(0xffffffffu, myw,   c0 & 31);
        unsigned f0 = __shfl_sync(0xffffffffu, myoff, c0 & 31);
        float    w1 = __shfl_sync(0xffffffffu, myw,   c1 & 31);
        unsigned f1 = __shfl_sync(0xffffffffu, myoff, c1 & 31);
        float    w2 = __shfl_sync(0xffffffffu, myw,   c2 & 31);
        unsigned f2 = __shfl_sync(0xffffffffu, myoff, c2 & 31);
        float    w3 = __shfl_sync(0xffffffffu, myw,   c3 & 31);
        unsigned f3 = __shfl_sync(0xffffffffu, myoff, c3 & 31);
        if (c1 < 0) w1 = 0.f;
        if (c2 < 0) w2 = 0.f;
        if (c3 < 0) w3 = 0.f;

        float4 a0 = make_float4(0.f,0.f,0.f,0.f), b0 = a0;
        float4 a1 = a0, b1 = a0, a2 = a0, b2 = a0, a3 = a0, b3 = a0;
        a0 = __ldg(vb4 + f0 + lane);
        b0 = __ldg(vb4 + f0 + 32 + lane);
        if (c1 >= 0) { a1 = __ldg(vb4 + f1 + lane); b1 = __ldg(vb4 + f1 + 32 + lane); }
        if (c2 >= 0) { a2 = __ldg(vb4 + f2 + lane); b2 = __ldg(vb4 + f2 + 32 + lane); }
        if (c3 >= 0) { a3 = __ldg(vb4 + f3 + lane); b3 = __ldg(vb4 + f3 + 32 + lane); }

        acc0.x = fmaf(w0, a0.x, acc0.x); acc0.y = fmaf(w0, a0.y, acc0.y);
        acc0.z = fmaf(w0, a0.z, acc0.z); acc0.w = fmaf(w0, a0.w, acc0.w);
        acc1.x = fmaf(w0, b0.x, acc1.x); acc1.y = fmaf(w0, b0.y, acc1.y);
        acc1.z = fmaf(w0, b0.z, acc1.z); acc1.w = fmaf(w0, b0.w, acc1.w);

        acc0.x = fmaf(w1, a1.x, acc0.x); acc0.y = fmaf(w1, a1.y, acc0.y);
        acc0.z = fmaf(w1, a1.z, acc0.z); acc0.w = fmaf(w1, a1.w, acc0.w);
        acc1.x = fmaf(w1, b1.x, acc1.x); acc1.y = fmaf(w1, b1.y, acc1.y);
        acc1.z = fmaf(w1, b1.z, acc1.z); acc1.w = fmaf(w1, b1.w, acc1.w);

        acc0.x = fmaf(w2, a2.x, acc0.x); acc0.y = fmaf(w2, a2.y, acc0.y);
        acc0.z = fmaf(w2, a2.z, acc0.z); acc0.w = fmaf(w2, a2.w, acc0.w);
        acc1.x = fmaf(w2, b2.x, acc1.x); acc1.y = fmaf(w2, b2.y, acc1.y);
        acc1.z = fmaf(w2, b2.z, acc1.z); acc1.w = fmaf(w2, b2.w, acc1.w);

        acc0.x = fmaf(w3, a3.x, acc0.x); acc0.y = fmaf(w3, a3.y, acc0.y);
        acc0.z = fmaf(w3, a3.z, acc0.z); acc0.w = fmaf(w3, a3.w, acc0.w);
        acc1.x = fmaf(w3, b3.x, acc1.x); acc1.y = fmaf(w3, b3.y, acc1.y);
        acc1.z = fmaf(w3, b3.z, acc1.z); acc1.w = fmaf(w3, b3.w, acc1.w);
    }
#undef GATHER_NOW

    float4* op = (float4*)(out + (size_t)q * CCH);
    op[lane]      = acc0;   // channels [4*lane, 4*lane+4)
    op[32 + lane] = acc1;   // channels [128+4*lane, ...)
}

extern "C" void kernel_launch(void* const* d_in, const int* in_sizes, int n_in,
                              void* d_out, int out_size)
{
    const float* query   = (const float*)d_in[0];
    // d_in[1] = key (unused)
    const float* value   = (const float*)d_in[2];
    const float* refpts  = (const float*)d_in[3];
    const int*   shapes  = (const int*)d_in[4];
    const float* W_off   = (const float*)d_in[5];
    const float* b_off   = (const float*)d_in[6];
    const float* W_attn  = (const float*)d_in[7];
    const float* b_attn  = (const float*)d_in[8];
    float*       out     = (float*)d_out;

    const int Q = in_sizes[0] / CCH;

    const int qpb = K1_WARPS * 16;
    proj_kernel<<<(Q + qpb - 1) / qpb, K1_WARPS * 32>>>(
        query, W_off, b_off, W_attn, b_attn, Q);
    sample_kernel<<<(Q + WPB - 1) / WPB, WPB * 32>>>(
        value, refpts, shapes, out, Q);
}